// round 12
// baseline (speedup 1.0000x reference)
#include <cuda_runtime.h>
#include <cstdint>
#include <cstddef>

#define BB 4
#define LL 4096
#define EPSF 1e-5f
#define YK (BB * LL * 128)
#define NW 8192            // scan warps (b4 * k4 * dp64 * chunk8)

__device__ __align__(256) float g_a   [BB * 64 * LL];
__device__ __align__(256) float g_b   [BB * 64 * LL];
__device__ __align__(256) float g_t0  [BB * 64 * LL];
__device__ __align__(256) float g_t1  [BB * 64 * LL];
__device__ __align__(256) float g_t2  [BB * 64 * LL];
__device__ __align__(256) float g_t3  [BB * 64 * LL];
__device__ __align__(256) float g_xin [BB * 128 * LL];
__device__ __align__(256) float g_xins[BB * 128 * LL];
__device__ __align__(256) float g_z   [BB * LL * 128];
__device__ __align__(256) float g_xdbl[BB * 4 * LL * 36];
__device__ __align__(256) float g_dtv [(size_t)BB * 4 * LL * 128];
__device__ __align__(256) float g_ydir[(size_t)4 * YK];
__device__ __align__(256) float g_P   [NW * 32];
__device__ __align__(256) float g_hz  [NW * 32];

// fast exp on the FMA pipe: no MUFU, no F2I/I2F
__device__ __forceinline__ float fexp(float p)
{
    p = fmaxf(p, -80.f);
    float y = fmaf(p, 1.442695041f, 12582912.f);
    int ei = __float_as_int(y) - 0x4B400000;
    float e = y - 12582912.f;
    float f = fmaf(p, 1.442695041f, -e);           // f in [-0.5, 0.5]
    float r = 1.5403530e-4f;
    r = fmaf(r, f, 1.3333558e-3f);
    r = fmaf(r, f, 9.6181291e-3f);
    r = fmaf(r, f, 5.5504109e-2f);
    r = fmaf(r, f, 2.4022651e-1f);
    r = fmaf(r, f, 6.9314718e-1f);
    r = fmaf(r, f, 1.0f);
    return __uint_as_float(__float_as_uint(r) + ((unsigned)ei << 23));
}

// ---------------- conv 3x3 SAME, 64->64, NCHW, cin-split partials -----------
// 64 threads; each thread: 4 vertical pixels x 8 output channels (32 acc).
// Input rows reused across dy taps: 6 LDS feed 96 FMAs per (cin, dx).
__global__ __launch_bounds__(64)
void conv3x3_k(const float* __restrict__ in, const float* __restrict__ w,
               float* __restrict__ p0, float* __restrict__ p1)
{
    __shared__ float s_in[8][18][18];
    __shared__ float s_w[8][9][8];
    const int tx = threadIdx.x & 15, tyq = threadIdx.x >> 4, tid = threadIdx.x;
    const int txt = blockIdx.x & 3, tyt = blockIdx.x >> 2;
    const int b = blockIdx.y;
    const int cog = blockIdx.z & 7, half = blockIdx.z >> 3;
    float* outp = half ? p1 : p0;
    const int cib = half << 5;

    float acc[4][8];
#pragma unroll
    for (int p = 0; p < 4; p++)
#pragma unroll
        for (int i = 0; i < 8; i++) acc[p][i] = 0.f;

    for (int ci0 = cib; ci0 < cib + 32; ci0 += 8) {
        for (int idx = tid; idx < 8 * 324; idx += 64) {
            int c2 = idx / 324, r = idx - c2 * 324;
            int iy = r / 18, ix = r - iy * 18;
            int gy = tyt * 16 + iy - 1, gx = txt * 16 + ix - 1;
            float v = 0.f;
            if ((unsigned)gy < 64u && (unsigned)gx < 64u)
                v = in[(((size_t)(b * 64 + ci0 + c2)) << 12) + (gy << 6) + gx];
            s_in[c2][iy][ix] = v;
        }
        for (int idx = tid; idx < 8 * 72; idx += 64) {
            int co2 = idx / 72, r = idx - co2 * 72;
            int c2 = r / 9, tap = r - c2 * 9;
            s_w[c2][tap][co2] = w[(((cog * 8 + co2) * 64) + ci0 + c2) * 9 + tap];
        }
        __syncthreads();
#pragma unroll
        for (int c2 = 0; c2 < 8; c2++) {
#pragma unroll
            for (int dx = 0; dx < 3; dx++) {
                float iv[6];
#pragma unroll
                for (int r = 0; r < 6; r++)
                    iv[r] = s_in[c2][tyq * 4 + r][tx + dx];
#pragma unroll
                for (int dy = 0; dy < 3; dy++) {
                    const float4* wp = (const float4*)&s_w[c2][dy * 3 + dx][0];
                    float4 w0 = wp[0], w1 = wp[1];
#pragma unroll
                    for (int p = 0; p < 4; p++) {
                        float v = iv[p + dy];
                        acc[p][0] = fmaf(v, w0.x, acc[p][0]);
                        acc[p][1] = fmaf(v, w0.y, acc[p][1]);
                        acc[p][2] = fmaf(v, w0.z, acc[p][2]);
                        acc[p][3] = fmaf(v, w0.w, acc[p][3]);
                        acc[p][4] = fmaf(v, w1.x, acc[p][4]);
                        acc[p][5] = fmaf(v, w1.y, acc[p][5]);
                        acc[p][6] = fmaf(v, w1.z, acc[p][6]);
                        acc[p][7] = fmaf(v, w1.w, acc[p][7]);
                    }
                }
            }
        }
        __syncthreads();
    }
    const int y0 = tyt * 16 + tyq * 4, x = txt * 16 + tx;
#pragma unroll
    for (int c = 0; c < 8; c++) {
        int co = cog * 8 + c;
        size_t off = (((size_t)(b * 64 + co)) << 12) + (y0 << 6) + x;
#pragma unroll
        for (int p = 0; p < 4; p++)
            outp[off + (p << 6)] = acc[p][c];
    }
}

// -------- combine partials + bias --------------------------------------------
__global__ __launch_bounds__(256)
void combine_k(float* __restrict__ dst, const float* __restrict__ p0,
               const float* __restrict__ p1, const float* __restrict__ bias)
{
    int i = ((blockIdx.x << 8) + threadIdx.x) << 2;
    float bv = __ldg(&bias[(i >> 12) & 63]);
    float4 a = *(const float4*)(p0 + i);
    float4 b4 = *(const float4*)(p1 + i);
    float4 r;
    r.x = a.x + b4.x + bv;  r.y = a.y + b4.y + bv;
    r.z = a.z + b4.z + bv;  r.w = a.w + b4.w + bv;
    *(float4*)(dst + i) = r;
}

// --- combine partials + bias (+ optional add0+add1+addb) + inorm + lrelu ----
__global__ __launch_bounds__(256)
void inorm2_k(const float* __restrict__ p0, const float* __restrict__ p1,
              const float* __restrict__ bias,
              const float* __restrict__ add0, const float* __restrict__ add1,
              const float* __restrict__ addb, float* __restrict__ out)
{
    size_t base = ((size_t)blockIdx.x) << 12;
    const int ch = blockIdx.x & 63;
    const float bv = __ldg(&bias[ch]);
    const float av = add0 ? __ldg(&addb[ch]) : 0.f;
    int t = threadIdx.x;
    float v[16], s = 0.f, ss = 0.f;
#pragma unroll
    for (int i = 0; i < 16; i++) {
        size_t o = base + t + (i << 8);
        float xv = p0[o] + p1[o] + bv;
        if (add0) xv += add0[o] + add1[o] + av;
        v[i] = xv; s += xv; ss += xv * xv;
    }
#pragma unroll
    for (int o = 16; o; o >>= 1) {
        s  += __shfl_xor_sync(0xffffffffu, s, o);
        ss += __shfl_xor_sync(0xffffffffu, ss, o);
    }
    __shared__ float sa[8], sb[8];
    if ((t & 31) == 0) { sa[t >> 5] = s; sb[t >> 5] = ss; }
    __syncthreads();
    s = 0.f; ss = 0.f;
#pragma unroll
    for (int i = 0; i < 8; i++) { s += sa[i]; ss += sb[i]; }
    float m = s * (1.f / 4096.f);
    float rs = rsqrtf(ss * (1.f / 4096.f) - m * m + EPSF);
#pragma unroll
    for (int i = 0; i < 16; i++) {
        float xv = (v[i] - m) * rs;
        out[base + t + (i << 8)] = xv >= 0.f ? xv : 0.2f * xv;
    }
}

// - channel LN of x1(=t0+t1+cfb) + in_proj (256 outs); xin NCHW, silu(z) -----
__global__ __launch_bounds__(256)
void ln_inproj_k(const float* __restrict__ ipw,
                 const float* __restrict__ lng, const float* __restrict__ lnb,
                 const float* __restrict__ cfb)
{
    __shared__ float s_xn[64][68];
    const int t = threadIdx.x;
    float4 wr[16];
    const float4* wp = (const float4*)(ipw + t * 64);
#pragma unroll
    for (int i = 0; i < 16; i++) wr[i] = wp[i];

    const int wid = t >> 5, ln = t & 31;
    const float lg1 = __ldg(&lng[ln]),      lb1 = __ldg(&lnb[ln]);
    const float lg2 = __ldg(&lng[ln + 32]), lb2 = __ldg(&lnb[ln + 32]);
    const float cb1 = __ldg(&cfb[ln]),      cb2 = __ldg(&cfb[ln + 32]);

    for (int pl = wid; pl < 64; pl += 8) {
        int p = blockIdx.x * 64 + pl;
        int b = p >> 12, pp = p & 4095;
        size_t o1 = (((size_t)(b * 64 + ln)) << 12) + pp;
        size_t o2 = (((size_t)(b * 64 + ln + 32)) << 12) + pp;
        float v1 = g_t0[o1] + g_t1[o1] + cb1;
        float v2 = g_t0[o2] + g_t1[o2] + cb2;
        float s = v1 + v2, ss = v1 * v1 + v2 * v2;
#pragma unroll
        for (int o = 16; o; o >>= 1) {
            s  += __shfl_xor_sync(0xffffffffu, s, o);
            ss += __shfl_xor_sync(0xffffffffu, ss, o);
        }
        float m = s * (1.f / 64.f);
        float rs = rsqrtf(ss * (1.f / 64.f) - m * m + EPSF);
        s_xn[pl][ln]      = (v1 - m) * rs * lg1 + lb1;
        s_xn[pl][ln + 32] = (v2 - m) * rs * lg2 + lb2;
    }
    __syncthreads();

    for (int pl = 0; pl < 64; pl++) {
        const float4* xr = (const float4*)&s_xn[pl][0];
        float acc = 0.f;
#pragma unroll
        for (int i = 0; i < 16; i++) {
            float4 xv = xr[i];
            acc = fmaf(wr[i].x, xv.x, acc);
            acc = fmaf(wr[i].y, xv.y, acc);
            acc = fmaf(wr[i].z, xv.z, acc);
            acc = fmaf(wr[i].w, xv.w, acc);
        }
        int p = blockIdx.x * 64 + pl;
        int b = p >> 12, pp = p & 4095;
        if (t < 128) {
            g_xin[(((size_t)(b * 128 + t)) << 12) + pp] = acc;
        } else {
            float sg = 1.f / (1.f + __expf(-acc));
            g_z[(((size_t)p) << 7) + (t - 128)] = acc * sg;
        }
    }
}

// ------------------- depthwise conv 3x3 + silu ------------------------------
__global__ __launch_bounds__(256)
void dwconv_silu_k(const float* __restrict__ dww, const float* __restrict__ dwb)
{
    int idx = (blockIdx.x << 8) + threadIdx.x;
    int pp = idx & 4095;
    int d = (idx >> 12) & 127;
    int y = pp >> 6, x = pp & 63;
    const float* ip = g_xin + (((size_t)(idx >> 12)) << 12);
    float acc = __ldg(&dwb[d]);
#pragma unroll
    for (int dy = -1; dy <= 1; dy++)
#pragma unroll
        for (int dx = -1; dx <= 1; dx++) {
            int yy = y + dy, xx = x + dx;
            if ((unsigned)yy < 64u && (unsigned)xx < 64u)
                acc = fmaf(ip[(yy << 6) + xx],
                           __ldg(&dww[d * 9 + (dy + 1) * 3 + dx + 1]), acc);
        }
    float sg = 1.f / (1.f + __expf(-acc));
    g_xins[idx] = acc * sg;
}

// ----- x_proj (B/C to gmem) + dt_proj + softplus fused; gather fused --------
__global__ __launch_bounds__(256)
void xdbl_k(const float* __restrict__ xpw,
            const float* __restrict__ dtw, const float* __restrict__ dtb)
{
    __shared__ float s_u[128 * 32];
    __shared__ float s_w[128 * 36 + 16];
    __shared__ float s_dts[32][4];
    __shared__ float s_dtw[512];
    const int bk = blockIdx.y, b = bk >> 2, k = bk & 3;
    const int l0 = blockIdx.x * 32, t = threadIdx.x;

    for (int idx = t; idx < 36 * 128; idx += 256) {
        int c = idx >> 7, d = idx & 127;
        s_w[d * 36 + c] = xpw[((k * 36 + c) << 7) + d];
    }
    for (int idx = t; idx < 512; idx += 256)
        s_dtw[idx] = dtw[(k << 9) + idx];
    for (int idx = t; idx < 128 * 32; idx += 256) {
        int d = idx >> 5, li = idx & 31;
        int l = l0 + li;
        int ls = (k >= 2) ? (4095 - l) : l;
        int mi = (k & 1) ? (((ls & 63) << 6) | (ls >> 6)) : ls;
        s_u[(d << 5) + li] = g_xins[(((size_t)(b * 128 + d)) << 12) + mi];
    }
    __syncthreads();

    const int li = t & 31, cq = t >> 5;
    float a0 = 0.f, a1 = 0.f, a2 = 0.f, a3 = 0.f, a4 = 0.f;
#pragma unroll 4
    for (int d = 0; d < 128; d++) {
        float u = s_u[(d << 5) + li];
        const float* wrow = &s_w[d * 36 + cq];
        a0 = fmaf(u, wrow[0],  a0);
        a1 = fmaf(u, wrow[8],  a1);
        a2 = fmaf(u, wrow[16], a2);
        a3 = fmaf(u, wrow[24], a3);
        a4 = fmaf(u, wrow[32], a4);
    }
    size_t base = ((size_t)bk * 4096 + l0 + li) * 36 + cq;
    if (cq >= 4) g_xdbl[base] = a0;      // B/C rows only; dts stays in smem
    else         s_dts[li][cq] = a0;
    g_xdbl[base + 8]  = a1;
    g_xdbl[base + 16] = a2;
    g_xdbl[base + 24] = a3;
    if (cq < 4) g_xdbl[base + 32] = a4;
    __syncthreads();

    const int d = t & 127, lgrp = t >> 7;
    const float4 wv = *(const float4*)&s_dtw[d << 2];
    const float db = __ldg(&dtb[(k << 7) + d]);
    float* dtvp = g_dtv + (((size_t)bk * 4096 + l0) << 7) + d;
#pragma unroll
    for (int j = 0; j < 16; j++) {
        int li2 = lgrp * 16 + j;
        float4 q = *(const float4*)&s_dts[li2][0];
        float xv = fmaf(q.x, wv.x, fmaf(q.y, wv.y, fmaf(q.z, wv.z, q.w * wv.w))) + db;
        float dtv = fmaxf(xv, 0.f) + __logf(1.f + __expf(-fabsf(xv)));
        dtvp[(size_t)li2 << 7] = dtv;
    }
}

// ----------------------- selective scan, chunked ----------------------------
__global__ __launch_bounds__(128)
void scan_p1(const float* __restrict__ A_logs)
{
    const int lane = threadIdx.x & 31;
    const int w = blockIdx.x * 4 + (threadIdx.x >> 5);
    const int c = w & 7, dp = (w >> 3) & 63, k = (w >> 9) & 3, b = w >> 11;
    const int d = dp * 2 + (lane >> 4);
    const int nn = lane & 15;
    const int kd = (k << 7) + d;
    const float A = -__expf(__ldg(&A_logs[(kd << 4) + nn]));
    const float* dt_base = g_dtv + (((size_t)(b * 4 + k)) << 19) + d;
    const float* xd = g_xdbl + ((size_t)(b * 4 + k)) * 4096 * 36;
    const float* u_base = g_xins + (((size_t)(b * 128 + d)) << 12);

    float h = 0.f, P = 1.f;
    const int tend = (c + 1) << 9;
    for (int t0 = c << 9; t0 < tend; t0 += 8) {
        float dtv[8], Bv[8], uu[8];
#pragma unroll
        for (int i = 0; i < 8; i++) {
            int t = t0 + i;
            int mi;
            if (k == 0)      mi = t;
            else if (k == 1) mi = ((t & 63) << 6) | (t >> 6);
            else if (k == 2) mi = 4095 - t;
            else { int s2 = 4095 - t; mi = ((s2 & 63) << 6) | (s2 >> 6); }
            dtv[i] = __ldg(dt_base + ((size_t)t << 7));
            Bv[i]  = __ldg(xd + (size_t)t * 36 + 4 + nn);
            uu[i]  = __ldg(u_base + mi);
        }
#pragma unroll
        for (int i = 0; i < 8; i++) {
            float a = fexp(dtv[i] * A);
            h = fmaf(h, a, (dtv[i] * uu[i]) * Bv[i]);
            P *= a;
        }
    }
    g_hz[(w << 5) + lane] = h;
    g_P [(w << 5) + lane] = P;
}

__global__ __launch_bounds__(128)
void scan_p2(const float* __restrict__ A_logs, const float* __restrict__ Dsp)
{
    const int lane = threadIdx.x & 31;
    const int w = blockIdx.x * 4 + (threadIdx.x >> 5);
    const int c = w & 7, dp = (w >> 3) & 63, k = (w >> 9) & 3, b = w >> 11;
    const int d = dp * 2 + (lane >> 4);
    const int nn = lane & 15;
    const int kd = (k << 7) + d;
    const float A = -__expf(__ldg(&A_logs[(kd << 4) + nn]));
    const float Dv = __ldg(&Dsp[kd]);
    const float* dt_base = g_dtv + (((size_t)(b * 4 + k)) << 19) + d;
    const float* xd = g_xdbl + ((size_t)(b * 4 + k)) * 4096 * 36;
    const float* u_base = g_xins + (((size_t)(b * 128 + d)) << 12);
    float* y_base = g_ydir + (size_t)k * YK + (((size_t)b) << 19) + d;

    float h = 0.f;
    for (int j = w - c; j < w; j++)
        h = fmaf(g_P[(j << 5) + lane], h, g_hz[(j << 5) + lane]);

    const int tend = (c + 1) << 9;
    for (int t0 = c << 9; t0 < tend; t0 += 8) {
        float dtv[8], Bv[8], Cv[8], uu[8]; int mi[8];
#pragma unroll
        for (int i = 0; i < 8; i++) {
            int t = t0 + i;
            if (k == 0)      mi[i] = t;
            else if (k == 1) mi[i] = ((t & 63) << 6) | (t >> 6);
            else if (k == 2) mi[i] = 4095 - t;
            else { int s2 = 4095 - t; mi[i] = ((s2 & 63) << 6) | (s2 >> 6); }
            dtv[i] = __ldg(dt_base + ((size_t)t << 7));
            Bv[i]  = __ldg(xd + (size_t)t * 36 + 4 + nn);
            Cv[i]  = __ldg(xd + (size_t)t * 36 + 20 + nn);
            uu[i]  = __ldg(u_base + mi[i]);
        }
#pragma unroll
        for (int i = 0; i < 8; i++) {
            float a = fexp(dtv[i] * A);
            h = fmaf(h, a, (dtv[i] * uu[i]) * Bv[i]);
            float py = h * Cv[i];
            py += __shfl_xor_sync(0xffffffffu, py, 1);
            py += __shfl_xor_sync(0xffffffffu, py, 2);
            py += __shfl_xor_sync(0xffffffffu, py, 4);
            py += __shfl_xor_sync(0xffffffffu, py, 8);
            if (nn == 0) y_base[((size_t)mi[i]) << 7] = fmaf(Dv, uu[i], py);
        }
    }
}

// - sum dirs, out-LN, *silu(z), out_proj, +skip*(t0+t1+cfb) -> res (NCHW) ----
__global__ __launch_bounds__(256)
void fuseout_k(const float* __restrict__ ong, const float* __restrict__ onb,
               const float* __restrict__ opw, const float* __restrict__ skipp,
               const float* __restrict__ cfb)
{
    __shared__ float s_opw[128 * 64];
    __shared__ float s_yn[8][132];
    const int t = threadIdx.x, wid = t >> 5, lane = t & 31;
    const float skip = __ldg(&skipp[0]);

    for (int idx = t; idx < 8192; idx += 256) {
        int c = idx >> 7, d = idx & 127;
        s_opw[(d << 6) + c] = opw[idx];
    }
    __syncthreads();

    const int d0 = lane << 2;
    const float4 gg = *(const float4*)(ong + d0);
    const float4 bb = *(const float4*)(onb + d0);
    const int c0 = lane, c1 = lane + 32;
    const float cb0 = __ldg(&cfb[c0]), cb1 = __ldg(&cfb[c1]);

    for (int i = 0; i < 4; i++) {
        int p = blockIdx.x * 32 + (wid << 2) + i;
        int b = p >> 12, l = p & 4095;
        size_t yo = (((size_t)p) << 7) + d0;
        float4 y  = *(const float4*)(g_ydir + yo);
        float4 y1 = *(const float4*)(g_ydir + (size_t)YK + yo);
        float4 y2 = *(const float4*)(g_ydir + 2 * (size_t)YK + yo);
        float4 y3 = *(const float4*)(g_ydir + 3 * (size_t)YK + yo);
        y.x += y1.x + y2.x + y3.x;  y.y += y1.y + y2.y + y3.y;
        y.z += y1.z + y2.z + y3.z;  y.w += y1.w + y2.w + y3.w;

        float s = y.x + y.y + y.z + y.w;
        float ss = y.x * y.x + y.y * y.y + y.z * y.z + y.w * y.w;
#pragma unroll
        for (int o = 16; o; o >>= 1) {
            s  += __shfl_xor_sync(0xffffffffu, s, o);
            ss += __shfl_xor_sync(0xffffffffu, ss, o);
        }
        float m = s * (1.f / 128.f);
        float rs = rsqrtf(ss * (1.f / 128.f) - m * m + EPSF);

        float4 zv = *(const float4*)(g_z + yo);
        float4 yn;
        yn.x = ((y.x - m) * rs * gg.x + bb.x) * zv.x;
        yn.y = ((y.y - m) * rs * gg.y + bb.y) * zv.y;
        yn.z = ((y.z - m) * rs * gg.z + bb.z) * zv.z;
        yn.w = ((y.w - m) * rs * gg.w + bb.w) * zv.w;
        __syncwarp();
        *(float4*)&s_yn[wid][d0] = yn;
        __syncwarp();

        float a0 = 0.f, a1 = 0.f;
#pragma unroll 8
        for (int d = 0; d < 128; d++) {
            float yv = s_yn[wid][d];
            a0 = fmaf(yv, s_opw[(d << 6) + c0], a0);
            a1 = fmaf(yv, s_opw[(d << 6) + c1], a1);
        }
        size_t o0 = (((size_t)(b * 64 + c0)) << 12) + l;
        size_t o1 = (((size_t)(b * 64 + c1)) << 12) + l;
        g_a[o0] = skip * (g_t0[o0] + g_t1[o0] + cb0) + a0;
        g_a[o1] = skip * (g_t0[o1] + g_t1[o1] + cb1) + a1;
    }
}

// ============================================================================
extern "C" void kernel_launch(void* const* d_in, const int* in_sizes, int n_in,
                              void* d_out, int out_size)
{
    const float* x       = (const float*)d_in[0];
    const float* conv1_w = (const float*)d_in[1];
    const float* conv1_b = (const float*)d_in[2];
    const float* conv2_w = (const float*)d_in[3];
    const float* conv2_b = (const float*)d_in[4];
    const float* cf_w    = (const float*)d_in[5];
    const float* cf_b    = (const float*)d_in[6];
    const float* ln_g    = (const float*)d_in[7];
    const float* ln_b    = (const float*)d_in[8];
    const float* in_proj = (const float*)d_in[9];
    const float* dw_w    = (const float*)d_in[10];
    const float* dw_b    = (const float*)d_in[11];
    const float* x_proj  = (const float*)d_in[12];
    const float* dt_w    = (const float*)d_in[13];
    const float* dt_b    = (const float*)d_in[14];
    const float* A_logs  = (const float*)d_in[15];
    const float* Ds      = (const float*)d_in[16];
    const float* on_g    = (const float*)d_in[17];
    const float* on_b    = (const float*)d_in[18];
    const float* op_w    = (const float*)d_in[19];
    const float* skip    = (const float*)d_in[20];
    const float* cb_w    = (const float*)d_in[21];
    const float* cb_b    = (const float*)d_in[22];
    float* out = (float*)d_out;

    float *ga, *gb, *t0, *t1, *t2, *t3;
    cudaGetSymbolAddress((void**)&ga, g_a);
    cudaGetSymbolAddress((void**)&gb, g_b);
    cudaGetSymbolAddress((void**)&t0, g_t0);
    cudaGetSymbolAddress((void**)&t1, g_t1);
    cudaGetSymbolAddress((void**)&t2, g_t2);
    cudaGetSymbolAddress((void**)&t3, g_t3);

    dim3 cgrid(16, 4, 16);
    conv3x3_k<<<cgrid, 64>>>(x, conv1_w, t0, t1);
    inorm2_k<<<256, 256>>>(t0, t1, conv1_b, nullptr, nullptr, nullptr, gb);
    conv3x3_k<<<cgrid, 64>>>(gb, conv2_w, t0, t1);
    combine_k<<<1024, 256>>>(ga, t0, t1, conv2_b);          // ga = mamba input
    conv3x3_k<<<cgrid, 64>>>(ga, cf_w, t0, t1);             // cf partials in t0,t1
    ln_inproj_k<<<256, 256>>>(in_proj, ln_g, ln_b, cf_b);
    dwconv_silu_k<<<8192, 256>>>(dw_w, dw_b);
    xdbl_k<<<dim3(128, 16), 256>>>(x_proj, dt_w, dt_b);
    scan_p1<<<NW / 4, 128>>>(A_logs);
    scan_p2<<<NW / 4, 128>>>(A_logs, Ds);
    fuseout_k<<<512, 256>>>(on_g, on_b, op_w, skip, cf_b);
    conv3x3_k<<<cgrid, 64>>>(ga, cb_w, t2, t3);
    inorm2_k<<<256, 256>>>(t2, t3, cb_b, t0, t1, cf_b, out);
}

// round 13
// speedup vs baseline: 1.1422x; 1.1422x over previous
#include <cuda_runtime.h>
#include <cstdint>
#include <cstddef>

#define BB 4
#define LL 4096
#define EPSF 1e-5f
#define YK (BB * LL * 128)
#define NW 8192            // scan warps (b4 * k4 * dp64 * chunk8)

__device__ __align__(256) float g_a   [BB * 64 * LL];
__device__ __align__(256) float g_b   [BB * 64 * LL];
__device__ __align__(256) float g_t0  [BB * 64 * LL];
__device__ __align__(256) float g_t1  [BB * 64 * LL];
__device__ __align__(256) float g_t2  [BB * 64 * LL];
__device__ __align__(256) float g_t3  [BB * 64 * LL];
__device__ __align__(256) float g_xin [BB * 128 * LL];
__device__ __align__(256) float g_xins[BB * 128 * LL];
__device__ __align__(256) float g_z   [BB * LL * 128];
__device__ __align__(256) float g_xdbl[BB * 4 * LL * 36];
__device__ __align__(256) float g_dtv [(size_t)BB * 4 * LL * 128];
__device__ __align__(256) float g_ydir[(size_t)4 * YK];
__device__ __align__(256) float g_P   [NW * 32];
__device__ __align__(256) float g_hz  [NW * 32];

// single-instruction exp2 on the MUFU pipe (issue-bound scan wants min inst)
__device__ __forceinline__ float fexp2(float x)
{
    float r;
    asm("ex2.approx.f32 %0, %1;" : "=f"(r) : "f"(x));
    return r;
}

// ---------------- conv 3x3 SAME, 64->64, NCHW, cin-split partials -----------
// (R11 version: 128 threads, 2 vertical px x 8 out channels)
__global__ __launch_bounds__(128)
void conv3x3_k(const float* __restrict__ in, const float* __restrict__ w,
               float* __restrict__ p0, float* __restrict__ p1)
{
    __shared__ float s_in[8][18][18];
    __shared__ float s_w[8][9][8];
    const int tx = threadIdx.x & 15, ty = threadIdx.x >> 4, tid = threadIdx.x;
    const int txt = blockIdx.x & 3, tyt = blockIdx.x >> 2;
    const int b = blockIdx.y;
    const int cog = blockIdx.z & 7, half = blockIdx.z >> 3;
    float* outp = half ? p1 : p0;
    const int cib = half << 5;

    float acc0[8], acc1[8];
#pragma unroll
    for (int i = 0; i < 8; i++) { acc0[i] = 0.f; acc1[i] = 0.f; }

    for (int ci0 = cib; ci0 < cib + 32; ci0 += 8) {
        for (int idx = tid; idx < 8 * 324; idx += 128) {
            int c2 = idx / 324, r = idx - c2 * 324;
            int iy = r / 18, ix = r - iy * 18;
            int gy = tyt * 16 + iy - 1, gx = txt * 16 + ix - 1;
            float v = 0.f;
            if ((unsigned)gy < 64u && (unsigned)gx < 64u)
                v = in[(((size_t)(b * 64 + ci0 + c2)) << 12) + (gy << 6) + gx];
            s_in[c2][iy][ix] = v;
        }
        for (int idx = tid; idx < 8 * 72; idx += 128) {
            int co2 = idx / 72, r = idx - co2 * 72;
            int c2 = r / 9, tap = r - c2 * 9;
            s_w[c2][tap][co2] = w[(((cog * 8 + co2) * 64) + ci0 + c2) * 9 + tap];
        }
        __syncthreads();
#pragma unroll
        for (int c2 = 0; c2 < 8; c2++)
#pragma unroll
            for (int tap = 0; tap < 9; tap++) {
                const int dy = tap / 3, dx = tap - dy * 3;
                float iv0 = s_in[c2][2 * ty + dy][tx + dx];
                float iv1 = s_in[c2][2 * ty + 1 + dy][tx + dx];
                const float4* wp = (const float4*)&s_w[c2][tap][0];
                float4 w0 = wp[0], w1 = wp[1];
                acc0[0] = fmaf(iv0, w0.x, acc0[0]);  acc1[0] = fmaf(iv1, w0.x, acc1[0]);
                acc0[1] = fmaf(iv0, w0.y, acc0[1]);  acc1[1] = fmaf(iv1, w0.y, acc1[1]);
                acc0[2] = fmaf(iv0, w0.z, acc0[2]);  acc1[2] = fmaf(iv1, w0.z, acc1[2]);
                acc0[3] = fmaf(iv0, w0.w, acc0[3]);  acc1[3] = fmaf(iv1, w0.w, acc1[3]);
                acc0[4] = fmaf(iv0, w1.x, acc0[4]);  acc1[4] = fmaf(iv1, w1.x, acc1[4]);
                acc0[5] = fmaf(iv0, w1.y, acc0[5]);  acc1[5] = fmaf(iv1, w1.y, acc1[5]);
                acc0[6] = fmaf(iv0, w1.z, acc0[6]);  acc1[6] = fmaf(iv1, w1.z, acc1[6]);
                acc0[7] = fmaf(iv0, w1.w, acc0[7]);  acc1[7] = fmaf(iv1, w1.w, acc1[7]);
            }
        __syncthreads();
    }
    const int y0 = tyt * 16 + 2 * ty, x = txt * 16 + tx;
#pragma unroll
    for (int c = 0; c < 8; c++) {
        int co = cog * 8 + c;
        size_t off0 = (((size_t)(b * 64 + co)) << 12) + (y0 << 6) + x;
        outp[off0] = acc0[c];
        outp[off0 + 64] = acc1[c];
    }
}

// -------- combine partials + bias --------------------------------------------
__global__ __launch_bounds__(256)
void combine_k(float* __restrict__ dst, const float* __restrict__ p0,
               const float* __restrict__ p1, const float* __restrict__ bias)
{
    int i = ((blockIdx.x << 8) + threadIdx.x) << 2;
    float bv = __ldg(&bias[(i >> 12) & 63]);
    float4 a = *(const float4*)(p0 + i);
    float4 b4 = *(const float4*)(p1 + i);
    float4 r;
    r.x = a.x + b4.x + bv;  r.y = a.y + b4.y + bv;
    r.z = a.z + b4.z + bv;  r.w = a.w + b4.w + bv;
    *(float4*)(dst + i) = r;
}

// --- combine partials + bias (+ optional add0+add1+addb) + inorm + lrelu ----
__global__ __launch_bounds__(256)
void inorm2_k(const float* __restrict__ p0, const float* __restrict__ p1,
              const float* __restrict__ bias,
              const float* __restrict__ add0, const float* __restrict__ add1,
              const float* __restrict__ addb, float* __restrict__ out)
{
    size_t base = ((size_t)blockIdx.x) << 12;
    const int ch = blockIdx.x & 63;
    const float bv = __ldg(&bias[ch]);
    const float av = add0 ? __ldg(&addb[ch]) : 0.f;
    int t = threadIdx.x;
    float v[16], s = 0.f, ss = 0.f;
#pragma unroll
    for (int i = 0; i < 16; i++) {
        size_t o = base + t + (i << 8);
        float xv = p0[o] + p1[o] + bv;
        if (add0) xv += add0[o] + add1[o] + av;
        v[i] = xv; s += xv; ss += xv * xv;
    }
#pragma unroll
    for (int o = 16; o; o >>= 1) {
        s  += __shfl_xor_sync(0xffffffffu, s, o);
        ss += __shfl_xor_sync(0xffffffffu, ss, o);
    }
    __shared__ float sa[8], sb[8];
    if ((t & 31) == 0) { sa[t >> 5] = s; sb[t >> 5] = ss; }
    __syncthreads();
    s = 0.f; ss = 0.f;
#pragma unroll
    for (int i = 0; i < 8; i++) { s += sa[i]; ss += sb[i]; }
    float m = s * (1.f / 4096.f);
    float rs = rsqrtf(ss * (1.f / 4096.f) - m * m + EPSF);
#pragma unroll
    for (int i = 0; i < 16; i++) {
        float xv = (v[i] - m) * rs;
        out[base + t + (i << 8)] = xv >= 0.f ? xv : 0.2f * xv;
    }
}

// - channel LN of x1(=t0+t1+cfb) + in_proj (256 outs); xin NCHW, silu(z) -----
__global__ __launch_bounds__(256)
void ln_inproj_k(const float* __restrict__ ipw,
                 const float* __restrict__ lng, const float* __restrict__ lnb,
                 const float* __restrict__ cfb)
{
    __shared__ float s_xn[64][68];
    const int t = threadIdx.x;
    float4 wr[16];
    const float4* wp = (const float4*)(ipw + t * 64);
#pragma unroll
    for (int i = 0; i < 16; i++) wr[i] = wp[i];

    const int wid = t >> 5, ln = t & 31;
    const float lg1 = __ldg(&lng[ln]),      lb1 = __ldg(&lnb[ln]);
    const float lg2 = __ldg(&lng[ln + 32]), lb2 = __ldg(&lnb[ln + 32]);
    const float cb1 = __ldg(&cfb[ln]),      cb2 = __ldg(&cfb[ln + 32]);

    for (int pl = wid; pl < 64; pl += 8) {
        int p = blockIdx.x * 64 + pl;
        int b = p >> 12, pp = p & 4095;
        size_t o1 = (((size_t)(b * 64 + ln)) << 12) + pp;
        size_t o2 = (((size_t)(b * 64 + ln + 32)) << 12) + pp;
        float v1 = g_t0[o1] + g_t1[o1] + cb1;
        float v2 = g_t0[o2] + g_t1[o2] + cb2;
        float s = v1 + v2, ss = v1 * v1 + v2 * v2;
#pragma unroll
        for (int o = 16; o; o >>= 1) {
            s  += __shfl_xor_sync(0xffffffffu, s, o);
            ss += __shfl_xor_sync(0xffffffffu, ss, o);
        }
        float m = s * (1.f / 64.f);
        float rs = rsqrtf(ss * (1.f / 64.f) - m * m + EPSF);
        s_xn[pl][ln]      = (v1 - m) * rs * lg1 + lb1;
        s_xn[pl][ln + 32] = (v2 - m) * rs * lg2 + lb2;
    }
    __syncthreads();

    for (int pl = 0; pl < 64; pl++) {
        const float4* xr = (const float4*)&s_xn[pl][0];
        float acc = 0.f;
#pragma unroll
        for (int i = 0; i < 16; i++) {
            float4 xv = xr[i];
            acc = fmaf(wr[i].x, xv.x, acc);
            acc = fmaf(wr[i].y, xv.y, acc);
            acc = fmaf(wr[i].z, xv.z, acc);
            acc = fmaf(wr[i].w, xv.w, acc);
        }
        int p = blockIdx.x * 64 + pl;
        int b = p >> 12, pp = p & 4095;
        if (t < 128) {
            g_xin[(((size_t)(b * 128 + t)) << 12) + pp] = acc;
        } else {
            float sg = 1.f / (1.f + __expf(-acc));
            g_z[(((size_t)p) << 7) + (t - 128)] = acc * sg;
        }
    }
}

// ------------------- depthwise conv 3x3 + silu ------------------------------
__global__ __launch_bounds__(256)
void dwconv_silu_k(const float* __restrict__ dww, const float* __restrict__ dwb)
{
    int idx = (blockIdx.x << 8) + threadIdx.x;
    int pp = idx & 4095;
    int d = (idx >> 12) & 127;
    int y = pp >> 6, x = pp & 63;
    const float* ip = g_xin + (((size_t)(idx >> 12)) << 12);
    float acc = __ldg(&dwb[d]);
#pragma unroll
    for (int dy = -1; dy <= 1; dy++)
#pragma unroll
        for (int dx = -1; dx <= 1; dx++) {
            int yy = y + dy, xx = x + dx;
            if ((unsigned)yy < 64u && (unsigned)xx < 64u)
                acc = fmaf(ip[(yy << 6) + xx],
                           __ldg(&dww[d * 9 + (dy + 1) * 3 + dx + 1]), acc);
        }
    float sg = 1.f / (1.f + __expf(-acc));
    g_xins[idx] = acc * sg;
}

// ----- x_proj (B/C to gmem) + dt_proj + softplus fused; gather fused --------
__global__ __launch_bounds__(256)
void xdbl_k(const float* __restrict__ xpw,
            const float* __restrict__ dtw, const float* __restrict__ dtb)
{
    __shared__ float s_u[128 * 32];
    __shared__ float s_w[128 * 36 + 16];
    __shared__ float s_dts[32][4];
    __shared__ float s_dtw[512];
    const int bk = blockIdx.y, b = bk >> 2, k = bk & 3;
    const int l0 = blockIdx.x * 32, t = threadIdx.x;

    for (int idx = t; idx < 36 * 128; idx += 256) {
        int c = idx >> 7, d = idx & 127;
        s_w[d * 36 + c] = xpw[((k * 36 + c) << 7) + d];
    }
    for (int idx = t; idx < 512; idx += 256)
        s_dtw[idx] = dtw[(k << 9) + idx];
    for (int idx = t; idx < 128 * 32; idx += 256) {
        int d = idx >> 5, li = idx & 31;
        int l = l0 + li;
        int ls = (k >= 2) ? (4095 - l) : l;
        int mi = (k & 1) ? (((ls & 63) << 6) | (ls >> 6)) : ls;
        s_u[(d << 5) + li] = g_xins[(((size_t)(b * 128 + d)) << 12) + mi];
    }
    __syncthreads();

    const int li = t & 31, cq = t >> 5;
    float a0 = 0.f, a1 = 0.f, a2 = 0.f, a3 = 0.f, a4 = 0.f;
#pragma unroll 4
    for (int d = 0; d < 128; d++) {
        float u = s_u[(d << 5) + li];
        const float* wrow = &s_w[d * 36 + cq];
        a0 = fmaf(u, wrow[0],  a0);
        a1 = fmaf(u, wrow[8],  a1);
        a2 = fmaf(u, wrow[16], a2);
        a3 = fmaf(u, wrow[24], a3);
        a4 = fmaf(u, wrow[32], a4);
    }
    size_t base = ((size_t)bk * 4096 + l0 + li) * 36 + cq;
    if (cq >= 4) g_xdbl[base] = a0;      // B/C rows only; dts stays in smem
    else         s_dts[li][cq] = a0;
    g_xdbl[base + 8]  = a1;
    g_xdbl[base + 16] = a2;
    g_xdbl[base + 24] = a3;
    if (cq < 4) g_xdbl[base + 32] = a4;
    __syncthreads();

    const int d = t & 127, lgrp = t >> 7;
    const float4 wv = *(const float4*)&s_dtw[d << 2];
    const float db = __ldg(&dtb[(k << 7) + d]);
    float* dtvp = g_dtv + (((size_t)bk * 4096 + l0) << 7) + d;
#pragma unroll
    for (int j = 0; j < 16; j++) {
        int li2 = lgrp * 16 + j;
        float4 q = *(const float4*)&s_dts[li2][0];
        float xv = fmaf(q.x, wv.x, fmaf(q.y, wv.y, fmaf(q.z, wv.z, q.w * wv.w))) + db;
        float dtv = fmaxf(xv, 0.f) + __logf(1.f + __expf(-fabsf(xv)));
        dtvp[(size_t)li2 << 7] = dtv;
    }
}

// ----------------------- selective scan, chunked ----------------------------
// a = exp(dt*A) = exp2(dt * A2), A2 = A*log2e, via 1 FMUL + 1 MUFU per step.
__global__ __launch_bounds__(128)
void scan_p1(const float* __restrict__ A_logs)
{
    const int lane = threadIdx.x & 31;
    const int w = blockIdx.x * 4 + (threadIdx.x >> 5);
    const int c = w & 7, dp = (w >> 3) & 63, k = (w >> 9) & 3, b = w >> 11;
    const int d = dp * 2 + (lane >> 4);
    const int nn = lane & 15;
    const int kd = (k << 7) + d;
    const float A2 = -__expf(__ldg(&A_logs[(kd << 4) + nn])) * 1.442695041f;
    const float* dt_base = g_dtv + (((size_t)(b * 4 + k)) << 19) + d;
    const float* xd = g_xdbl + ((size_t)(b * 4 + k)) * 4096 * 36;
    const float* u_base = g_xins + (((size_t)(b * 128 + d)) << 12);

    float h = 0.f, P = 1.f;
    const int tend = (c + 1) << 9;
    for (int t0 = c << 9; t0 < tend; t0 += 8) {
        float dtv[8], Bv[8], uu[8];
#pragma unroll
        for (int i = 0; i < 8; i++) {
            int t = t0 + i;
            int mi;
            if (k == 0)      mi = t;
            else if (k == 1) mi = ((t & 63) << 6) | (t >> 6);
            else if (k == 2) mi = 4095 - t;
            else { int s2 = 4095 - t; mi = ((s2 & 63) << 6) | (s2 >> 6); }
            dtv[i] = __ldg(dt_base + ((size_t)t << 7));
            Bv[i]  = __ldg(xd + (size_t)t * 36 + 4 + nn);
            uu[i]  = __ldg(u_base + mi);
        }
#pragma unroll
        for (int i = 0; i < 8; i++) {
            float a = fexp2(dtv[i] * A2);
            h = fmaf(h, a, (dtv[i] * uu[i]) * Bv[i]);
            P *= a;
        }
    }
    g_hz[(w << 5) + lane] = h;
    g_P [(w << 5) + lane] = P;
}

__global__ __launch_bounds__(128)
void scan_p2(const float* __restrict__ A_logs, const float* __restrict__ Dsp)
{
    const int lane = threadIdx.x & 31;
    const int w = blockIdx.x * 4 + (threadIdx.x >> 5);
    const int c = w & 7, dp = (w >> 3) & 63, k = (w >> 9) & 3, b = w >> 11;
    const int d = dp * 2 + (lane >> 4);
    const int nn = lane & 15;
    const int kd = (k << 7) + d;
    const float A2 = -__expf(__ldg(&A_logs[(kd << 4) + nn])) * 1.442695041f;
    const float Dv = __ldg(&Dsp[kd]);
    const float* dt_base = g_dtv + (((size_t)(b * 4 + k)) << 19) + d;
    const float* xd = g_xdbl + ((size_t)(b * 4 + k)) * 4096 * 36;
    const float* u_base = g_xins + (((size_t)(b * 128 + d)) << 12);
    float* y_base = g_ydir + (size_t)k * YK + (((size_t)b) << 19) + d;

    float h = 0.f;
    for (int j = w - c; j < w; j++)
        h = fmaf(g_P[(j << 5) + lane], h, g_hz[(j << 5) + lane]);

    const int tend = (c + 1) << 9;
    for (int t0 = c << 9; t0 < tend; t0 += 8) {
        float dtv[8], Bv[8], Cv[8], uu[8]; int mi[8];
#pragma unroll
        for (int i = 0; i < 8; i++) {
            int t = t0 + i;
            if (k == 0)      mi[i] = t;
            else if (k == 1) mi[i] = ((t & 63) << 6) | (t >> 6);
            else if (k == 2) mi[i] = 4095 - t;
            else { int s2 = 4095 - t; mi[i] = ((s2 & 63) << 6) | (s2 >> 6); }
            dtv[i] = __ldg(dt_base + ((size_t)t << 7));
            Bv[i]  = __ldg(xd + (size_t)t * 36 + 4 + nn);
            Cv[i]  = __ldg(xd + (size_t)t * 36 + 20 + nn);
            uu[i]  = __ldg(u_base + mi[i]);
        }
#pragma unroll
        for (int i = 0; i < 8; i++) {
            float a = fexp2(dtv[i] * A2);
            h = fmaf(h, a, (dtv[i] * uu[i]) * Bv[i]);
            float py = h * Cv[i];
            py += __shfl_xor_sync(0xffffffffu, py, 1);
            py += __shfl_xor_sync(0xffffffffu, py, 2);
            py += __shfl_xor_sync(0xffffffffu, py, 4);
            py += __shfl_xor_sync(0xffffffffu, py, 8);
            if (nn == 0) y_base[((size_t)mi[i]) << 7] = fmaf(Dv, uu[i], py);
        }
    }
}

// - sum dirs, out-LN, *silu(z), out_proj, +skip*(t0+t1+cfb) -> res (NCHW) ----
__global__ __launch_bounds__(256)
void fuseout_k(const float* __restrict__ ong, const float* __restrict__ onb,
               const float* __restrict__ opw, const float* __restrict__ skipp,
               const float* __restrict__ cfb)
{
    __shared__ float s_opw[128 * 64];
    __shared__ float s_yn[8][132];
    const int t = threadIdx.x, wid = t >> 5, lane = t & 31;
    const float skip = __ldg(&skipp[0]);

    for (int idx = t; idx < 8192; idx += 256) {
        int c = idx >> 7, d = idx & 127;
        s_opw[(d << 6) + c] = opw[idx];
    }
    __syncthreads();

    const int d0 = lane << 2;
    const float4 gg = *(const float4*)(ong + d0);
    const float4 bb = *(const float4*)(onb + d0);
    const int c0 = lane, c1 = lane + 32;
    const float cb0 = __ldg(&cfb[c0]), cb1 = __ldg(&cfb[c1]);

    for (int i = 0; i < 4; i++) {
        int p = blockIdx.x * 32 + (wid << 2) + i;
        int b = p >> 12, l = p & 4095;
        size_t yo = (((size_t)p) << 7) + d0;
        float4 y  = *(const float4*)(g_ydir + yo);
        float4 y1 = *(const float4*)(g_ydir + (size_t)YK + yo);
        float4 y2 = *(const float4*)(g_ydir + 2 * (size_t)YK + yo);
        float4 y3 = *(const float4*)(g_ydir + 3 * (size_t)YK + yo);
        y.x += y1.x + y2.x + y3.x;  y.y += y1.y + y2.y + y3.y;
        y.z += y1.z + y2.z + y3.z;  y.w += y1.w + y2.w + y3.w;

        float s = y.x + y.y + y.z + y.w;
        float ss = y.x * y.x + y.y * y.y + y.z * y.z + y.w * y.w;
#pragma unroll
        for (int o = 16; o; o >>= 1) {
            s  += __shfl_xor_sync(0xffffffffu, s, o);
            ss += __shfl_xor_sync(0xffffffffu, ss, o);
        }
        float m = s * (1.f / 128.f);
        float rs = rsqrtf(ss * (1.f / 128.f) - m * m + EPSF);

        float4 zv = *(const float4*)(g_z + yo);
        float4 yn;
        yn.x = ((y.x - m) * rs * gg.x + bb.x) * zv.x;
        yn.y = ((y.y - m) * rs * gg.y + bb.y) * zv.y;
        yn.z = ((y.z - m) * rs * gg.z + bb.z) * zv.z;
        yn.w = ((y.w - m) * rs * gg.w + bb.w) * zv.w;
        __syncwarp();
        *(float4*)&s_yn[wid][d0] = yn;
        __syncwarp();

        float a0 = 0.f, a1 = 0.f;
#pragma unroll 8
        for (int d = 0; d < 128; d++) {
            float yv = s_yn[wid][d];
            a0 = fmaf(yv, s_opw[(d << 6) + c0], a0);
            a1 = fmaf(yv, s_opw[(d << 6) + c1], a1);
        }
        size_t o0 = (((size_t)(b * 64 + c0)) << 12) + l;
        size_t o1 = (((size_t)(b * 64 + c1)) << 12) + l;
        g_a[o0] = skip * (g_t0[o0] + g_t1[o0] + cb0) + a0;
        g_a[o1] = skip * (g_t0[o1] + g_t1[o1] + cb1) + a1;
    }
}

// ============================================================================
extern "C" void kernel_launch(void* const* d_in, const int* in_sizes, int n_in,
                              void* d_out, int out_size)
{
    const float* x       = (const float*)d_in[0];
    const float* conv1_w = (const float*)d_in[1];
    const float* conv1_b = (const float*)d_in[2];
    const float* conv2_w = (const float*)d_in[3];
    const float* conv2_b = (const float*)d_in[4];
    const float* cf_w    = (const float*)d_in[5];
    const float* cf_b    = (const float*)d_in[6];
    const float* ln_g    = (const float*)d_in[7];
    const float* ln_b    = (const float*)d_in[8];
    const float* in_proj = (const float*)d_in[9];
    const float* dw_w    = (const float*)d_in[10];
    const float* dw_b    = (const float*)d_in[11];
    const float* x_proj  = (const float*)d_in[12];
    const float* dt_w    = (const float*)d_in[13];
    const float* dt_b    = (const float*)d_in[14];
    const float* A_logs  = (const float*)d_in[15];
    const float* Ds      = (const float*)d_in[16];
    const float* on_g    = (const float*)d_in[17];
    const float* on_b    = (const float*)d_in[18];
    const float* op_w    = (const float*)d_in[19];
    const float* skip    = (const float*)d_in[20];
    const float* cb_w    = (const float*)d_in[21];
    const float* cb_b    = (const float*)d_in[22];
    float* out = (float*)d_out;

    float *ga, *gb, *t0, *t1, *t2, *t3;
    cudaGetSymbolAddress((void**)&ga, g_a);
    cudaGetSymbolAddress((void**)&gb, g_b);
    cudaGetSymbolAddress((void**)&t0, g_t0);
    cudaGetSymbolAddress((void**)&t1, g_t1);
    cudaGetSymbolAddress((void**)&t2, g_t2);
    cudaGetSymbolAddress((void**)&t3, g_t3);

    dim3 cgrid(16, 4, 16);
    conv3x3_k<<<cgrid, 128>>>(x, conv1_w, t0, t1);
    inorm2_k<<<256, 256>>>(t0, t1, conv1_b, nullptr, nullptr, nullptr, gb);
    conv3x3_k<<<cgrid, 128>>>(gb, conv2_w, t0, t1);
    combine_k<<<1024, 256>>>(ga, t0, t1, conv2_b);          // ga = mamba input
    conv3x3_k<<<cgrid, 128>>>(ga, cf_w, t0, t1);            // cf partials in t0,t1
    ln_inproj_k<<<256, 256>>>(in_proj, ln_g, ln_b, cf_b);
    dwconv_silu_k<<<8192, 256>>>(dw_w, dw_b);
    xdbl_k<<<dim3(128, 16), 256>>>(x_proj, dt_w, dt_b);
    scan_p1<<<NW / 4, 128>>>(A_logs);
    scan_p2<<<NW / 4, 128>>>(A_logs, Ds);
    fuseout_k<<<512, 256>>>(on_g, on_b, op_w, skip, cf_b);
    conv3x3_k<<<cgrid, 128>>>(ga, cb_w, t2, t3);
    inorm2_k<<<256, 256>>>(t2, t3, cb_b, t0, t1, cf_b, out);
}

// round 14
// speedup vs baseline: 1.2176x; 1.0660x over previous
#include <cuda_runtime.h>
#include <cstdint>
#include <cstddef>

#define BB 4
#define LL 4096
#define EPSF 1e-5f
#define YK (BB * LL * 128)
#define NW 8192            // scan warps (b4 * k4 * dp64 * chunk8)

__device__ __align__(256) float g_a   [BB * 64 * LL];
__device__ __align__(256) float g_b   [BB * 64 * LL];
__device__ __align__(256) float g_t0  [BB * 64 * LL];
__device__ __align__(256) float g_t1  [BB * 64 * LL];
__device__ __align__(256) float g_t2  [BB * 64 * LL];
__device__ __align__(256) float g_t3  [BB * 64 * LL];
__device__ __align__(256) float g_xin [BB * 128 * LL];
__device__ __align__(256) float g_xins[BB * 128 * LL];
__device__ __align__(256) float g_z   [BB * LL * 128];
__device__ __align__(256) float g_xdbl[BB * 4 * LL * 36];
__device__ __align__(256) float g_dtv [(size_t)BB * 4 * LL * 128];
__device__ __align__(256) float g_ydir[(size_t)4 * YK];
__device__ __align__(256) float g_P   [NW * 32];
__device__ __align__(256) float g_hz  [NW * 32];

// single-instruction exp2 on the MUFU pipe
__device__ __forceinline__ float fexp2(float x)
{
    float r;
    asm("ex2.approx.f32 %0, %1;" : "=f"(r) : "f"(x));
    return r;
}

// ---------------- conv 3x3 SAME, 64->64, NCHW, cin-split partials -----------
// 128 threads, 2 vertical px x 8 out channels. Register-prefetch pipeline:
// chunk N+1's global loads land in registers while chunk N computes.
__global__ __launch_bounds__(128)
void conv3x3_k(const float* __restrict__ in, const float* __restrict__ w,
               float* __restrict__ p0, float* __restrict__ p1)
{
    __shared__ float s_in[2592];   // [c2][iy][ix] = c2*324 + iy*18 + ix
    __shared__ float s_w[576];     // [c2][tap][co2] = c2*72 + tap*8 + co2
    const int tx = threadIdx.x & 15, ty = threadIdx.x >> 4, tid = threadIdx.x;
    const int txt = blockIdx.x & 3, tyt = blockIdx.x >> 2;
    const int b = blockIdx.y;
    const int cog = blockIdx.z & 7, half = blockIdx.z >> 3;
    float* outp = half ? p1 : p0;
    const int cib = half << 5;

    float acc0[8], acc1[8];
#pragma unroll
    for (int i = 0; i < 8; i++) { acc0[i] = 0.f; acc1[i] = 0.f; }

    float rin[21], rw[5];
    // initial prefetch (chunk 0)
    {
        const int ci0 = cib;
#pragma unroll
        for (int j = 0; j < 21; j++) {
            int idx = tid + (j << 7);
            float v = 0.f;
            if (j < 20 || idx < 2592) {
                int c2 = idx / 324, r = idx - c2 * 324;
                int iy = r / 18, ix = r - iy * 18;
                int gy = tyt * 16 + iy - 1, gx = txt * 16 + ix - 1;
                if ((unsigned)gy < 64u && (unsigned)gx < 64u)
                    v = in[(((size_t)(b * 64 + ci0 + c2)) << 12) + (gy << 6) + gx];
            }
            rin[j] = v;
        }
#pragma unroll
        for (int j = 0; j < 5; j++) {
            int idx = tid + (j << 7);
            if (j < 4 || idx < 576) {
                int co2 = idx / 72, r = idx - co2 * 72;
                int c2 = r / 9, tap = r - c2 * 9;
                rw[j] = w[(((cog * 8 + co2) * 64) + ci0 + c2) * 9 + tap];
            }
        }
    }

    for (int chunk = 0; chunk < 4; chunk++) {
        __syncthreads();                       // prior compute done -> safe to overwrite
#pragma unroll
        for (int j = 0; j < 21; j++) {
            int idx = tid + (j << 7);
            if (j < 20 || idx < 2592) s_in[idx] = rin[j];
        }
#pragma unroll
        for (int j = 0; j < 5; j++) {
            int idx = tid + (j << 7);
            if (j < 4 || idx < 576) {
                int co2 = idx / 72, r = idx - co2 * 72;
                int c2 = r / 9, tap = r - c2 * 9;
                s_w[c2 * 72 + tap * 8 + co2] = rw[j];
            }
        }
        __syncthreads();                       // tiles visible

        if (chunk < 3) {                       // prefetch next chunk into regs
            const int ci0 = cib + (chunk + 1) * 8;
#pragma unroll
            for (int j = 0; j < 21; j++) {
                int idx = tid + (j << 7);
                float v = 0.f;
                if (j < 20 || idx < 2592) {
                    int c2 = idx / 324, r = idx - c2 * 324;
                    int iy = r / 18, ix = r - iy * 18;
                    int gy = tyt * 16 + iy - 1, gx = txt * 16 + ix - 1;
                    if ((unsigned)gy < 64u && (unsigned)gx < 64u)
                        v = in[(((size_t)(b * 64 + ci0 + c2)) << 12) + (gy << 6) + gx];
                }
                rin[j] = v;
            }
#pragma unroll
            for (int j = 0; j < 5; j++) {
                int idx = tid + (j << 7);
                if (j < 4 || idx < 576) {
                    int co2 = idx / 72, r = idx - co2 * 72;
                    int c2 = r / 9, tap = r - c2 * 9;
                    rw[j] = w[(((cog * 8 + co2) * 64) + ci0 + c2) * 9 + tap];
                }
            }
        }

#pragma unroll
        for (int c2 = 0; c2 < 8; c2++)
#pragma unroll
            for (int tap = 0; tap < 9; tap++) {
                const int dy = tap / 3, dx = tap - dy * 3;
                float iv0 = s_in[c2 * 324 + (2 * ty + dy) * 18 + tx + dx];
                float iv1 = s_in[c2 * 324 + (2 * ty + 1 + dy) * 18 + tx + dx];
                const float4* wp = (const float4*)&s_w[c2 * 72 + tap * 8];
                float4 w0 = wp[0], w1 = wp[1];
                acc0[0] = fmaf(iv0, w0.x, acc0[0]);  acc1[0] = fmaf(iv1, w0.x, acc1[0]);
                acc0[1] = fmaf(iv0, w0.y, acc0[1]);  acc1[1] = fmaf(iv1, w0.y, acc1[1]);
                acc0[2] = fmaf(iv0, w0.z, acc0[2]);  acc1[2] = fmaf(iv1, w0.z, acc1[2]);
                acc0[3] = fmaf(iv0, w0.w, acc0[3]);  acc1[3] = fmaf(iv1, w0.w, acc1[3]);
                acc0[4] = fmaf(iv0, w1.x, acc0[4]);  acc1[4] = fmaf(iv1, w1.x, acc1[4]);
                acc0[5] = fmaf(iv0, w1.y, acc0[5]);  acc1[5] = fmaf(iv1, w1.y, acc1[5]);
                acc0[6] = fmaf(iv0, w1.z, acc0[6]);  acc1[6] = fmaf(iv1, w1.z, acc1[6]);
                acc0[7] = fmaf(iv0, w1.w, acc0[7]);  acc1[7] = fmaf(iv1, w1.w, acc1[7]);
            }
    }
    const int y0 = tyt * 16 + 2 * ty, x = txt * 16 + tx;
#pragma unroll
    for (int c = 0; c < 8; c++) {
        int co = cog * 8 + c;
        size_t off0 = (((size_t)(b * 64 + co)) << 12) + (y0 << 6) + x;
        outp[off0] = acc0[c];
        outp[off0 + 64] = acc1[c];
    }
}

// -------- combine partials + bias --------------------------------------------
__global__ __launch_bounds__(256)
void combine_k(float* __restrict__ dst, const float* __restrict__ p0,
               const float* __restrict__ p1, const float* __restrict__ bias)
{
    int i = ((blockIdx.x << 8) + threadIdx.x) << 2;
    float bv = __ldg(&bias[(i >> 12) & 63]);
    float4 a = *(const float4*)(p0 + i);
    float4 b4 = *(const float4*)(p1 + i);
    float4 r;
    r.x = a.x + b4.x + bv;  r.y = a.y + b4.y + bv;
    r.z = a.z + b4.z + bv;  r.w = a.w + b4.w + bv;
    *(float4*)(dst + i) = r;
}

// --- combine partials + bias (+ optional add0+add1+addb) + inorm + lrelu ----
__global__ __launch_bounds__(256)
void inorm2_k(const float* __restrict__ p0, const float* __restrict__ p1,
              const float* __restrict__ bias,
              const float* __restrict__ add0, const float* __restrict__ add1,
              const float* __restrict__ addb, float* __restrict__ out)
{
    size_t base = ((size_t)blockIdx.x) << 12;
    const int ch = blockIdx.x & 63;
    const float bv = __ldg(&bias[ch]);
    const float av = add0 ? __ldg(&addb[ch]) : 0.f;
    int t = threadIdx.x;
    float v[16], s = 0.f, ss = 0.f;
#pragma unroll
    for (int i = 0; i < 16; i++) {
        size_t o = base + t + (i << 8);
        float xv = p0[o] + p1[o] + bv;
        if (add0) xv += add0[o] + add1[o] + av;
        v[i] = xv; s += xv; ss += xv * xv;
    }
#pragma unroll
    for (int o = 16; o; o >>= 1) {
        s  += __shfl_xor_sync(0xffffffffu, s, o);
        ss += __shfl_xor_sync(0xffffffffu, ss, o);
    }
    __shared__ float sa[8], sb[8];
    if ((t & 31) == 0) { sa[t >> 5] = s; sb[t >> 5] = ss; }
    __syncthreads();
    s = 0.f; ss = 0.f;
#pragma unroll
    for (int i = 0; i < 8; i++) { s += sa[i]; ss += sb[i]; }
    float m = s * (1.f / 4096.f);
    float rs = rsqrtf(ss * (1.f / 4096.f) - m * m + EPSF);
#pragma unroll
    for (int i = 0; i < 16; i++) {
        float xv = (v[i] - m) * rs;
        out[base + t + (i << 8)] = xv >= 0.f ? xv : 0.2f * xv;
    }
}

// - channel LN of x1(=t0+t1+cfb) + in_proj (256 outs); xin NCHW, silu(z) -----
__global__ __launch_bounds__(256)
void ln_inproj_k(const float* __restrict__ ipw,
                 const float* __restrict__ lng, const float* __restrict__ lnb,
                 const float* __restrict__ cfb)
{
    __shared__ float s_xn[64][68];
    const int t = threadIdx.x;
    float4 wr[16];
    const float4* wp = (const float4*)(ipw + t * 64);
#pragma unroll
    for (int i = 0; i < 16; i++) wr[i] = wp[i];

    const int wid = t >> 5, ln = t & 31;
    const float lg1 = __ldg(&lng[ln]),      lb1 = __ldg(&lnb[ln]);
    const float lg2 = __ldg(&lng[ln + 32]), lb2 = __ldg(&lnb[ln + 32]);
    const float cb1 = __ldg(&cfb[ln]),      cb2 = __ldg(&cfb[ln + 32]);

    for (int pl = wid; pl < 64; pl += 8) {
        int p = blockIdx.x * 64 + pl;
        int b = p >> 12, pp = p & 4095;
        size_t o1 = (((size_t)(b * 64 + ln)) << 12) + pp;
        size_t o2 = (((size_t)(b * 64 + ln + 32)) << 12) + pp;
        float v1 = g_t0[o1] + g_t1[o1] + cb1;
        float v2 = g_t0[o2] + g_t1[o2] + cb2;
        float s = v1 + v2, ss = v1 * v1 + v2 * v2;
#pragma unroll
        for (int o = 16; o; o >>= 1) {
            s  += __shfl_xor_sync(0xffffffffu, s, o);
            ss += __shfl_xor_sync(0xffffffffu, ss, o);
        }
        float m = s * (1.f / 64.f);
        float rs = rsqrtf(ss * (1.f / 64.f) - m * m + EPSF);
        s_xn[pl][ln]      = (v1 - m) * rs * lg1 + lb1;
        s_xn[pl][ln + 32] = (v2 - m) * rs * lg2 + lb2;
    }
    __syncthreads();

    for (int pl = 0; pl < 64; pl++) {
        const float4* xr = (const float4*)&s_xn[pl][0];
        float acc = 0.f;
#pragma unroll
        for (int i = 0; i < 16; i++) {
            float4 xv = xr[i];
            acc = fmaf(wr[i].x, xv.x, acc);
            acc = fmaf(wr[i].y, xv.y, acc);
            acc = fmaf(wr[i].z, xv.z, acc);
            acc = fmaf(wr[i].w, xv.w, acc);
        }
        int p = blockIdx.x * 64 + pl;
        int b = p >> 12, pp = p & 4095;
        if (t < 128) {
            g_xin[(((size_t)(b * 128 + t)) << 12) + pp] = acc;
        } else {
            float sg = 1.f / (1.f + __expf(-acc));
            g_z[(((size_t)p) << 7) + (t - 128)] = acc * sg;
        }
    }
}

// ------------------- depthwise conv 3x3 + silu ------------------------------
__global__ __launch_bounds__(256)
void dwconv_silu_k(const float* __restrict__ dww, const float* __restrict__ dwb)
{
    int idx = (blockIdx.x << 8) + threadIdx.x;
    int pp = idx & 4095;
    int d = (idx >> 12) & 127;
    int y = pp >> 6, x = pp & 63;
    const float* ip = g_xin + (((size_t)(idx >> 12)) << 12);
    float acc = __ldg(&dwb[d]);
#pragma unroll
    for (int dy = -1; dy <= 1; dy++)
#pragma unroll
        for (int dx = -1; dx <= 1; dx++) {
            int yy = y + dy, xx = x + dx;
            if ((unsigned)yy < 64u && (unsigned)xx < 64u)
                acc = fmaf(ip[(yy << 6) + xx],
                           __ldg(&dww[d * 9 + (dy + 1) * 3 + dx + 1]), acc);
        }
    float sg = 1.f / (1.f + __expf(-acc));
    g_xins[idx] = acc * sg;
}

// ----- x_proj (B/C to gmem) + dt_proj + softplus fused; gather fused --------
__global__ __launch_bounds__(256)
void xdbl_k(const float* __restrict__ xpw,
            const float* __restrict__ dtw, const float* __restrict__ dtb)
{
    __shared__ float s_u[128 * 32];
    __shared__ float s_w[128 * 36 + 16];
    __shared__ float s_dts[32][4];
    __shared__ float s_dtw[512];
    const int bk = blockIdx.y, b = bk >> 2, k = bk & 3;
    const int l0 = blockIdx.x * 32, t = threadIdx.x;

    for (int idx = t; idx < 36 * 128; idx += 256) {
        int c = idx >> 7, d = idx & 127;
        s_w[d * 36 + c] = xpw[((k * 36 + c) << 7) + d];
    }
    for (int idx = t; idx < 512; idx += 256)
        s_dtw[idx] = dtw[(k << 9) + idx];
    for (int idx = t; idx < 128 * 32; idx += 256) {
        int d = idx >> 5, li = idx & 31;
        int l = l0 + li;
        int ls = (k >= 2) ? (4095 - l) : l;
        int mi = (k & 1) ? (((ls & 63) << 6) | (ls >> 6)) : ls;
        s_u[(d << 5) + li] = g_xins[(((size_t)(b * 128 + d)) << 12) + mi];
    }
    __syncthreads();

    const int li = t & 31, cq = t >> 5;
    float a0 = 0.f, a1 = 0.f, a2 = 0.f, a3 = 0.f, a4 = 0.f;
#pragma unroll 4
    for (int d = 0; d < 128; d++) {
        float u = s_u[(d << 5) + li];
        const float* wrow = &s_w[d * 36 + cq];
        a0 = fmaf(u, wrow[0],  a0);
        a1 = fmaf(u, wrow[8],  a1);
        a2 = fmaf(u, wrow[16], a2);
        a3 = fmaf(u, wrow[24], a3);
        a4 = fmaf(u, wrow[32], a4);
    }
    size_t base = ((size_t)bk * 4096 + l0 + li) * 36 + cq;
    if (cq >= 4) g_xdbl[base] = a0;      // B/C rows only; dts stays in smem
    else         s_dts[li][cq] = a0;
    g_xdbl[base + 8]  = a1;
    g_xdbl[base + 16] = a2;
    g_xdbl[base + 24] = a3;
    if (cq < 4) g_xdbl[base + 32] = a4;
    __syncthreads();

    const int d = t & 127, lgrp = t >> 7;
    const float4 wv = *(const float4*)&s_dtw[d << 2];
    const float db = __ldg(&dtb[(k << 7) + d]);
    float* dtvp = g_dtv + (((size_t)bk * 4096 + l0) << 7) + d;
#pragma unroll
    for (int j = 0; j < 16; j++) {
        int li2 = lgrp * 16 + j;
        float4 q = *(const float4*)&s_dts[li2][0];
        float xv = fmaf(q.x, wv.x, fmaf(q.y, wv.y, fmaf(q.z, wv.z, q.w * wv.w))) + db;
        float dtv = fmaxf(xv, 0.f) + __logf(1.f + __expf(-fabsf(xv)));
        dtvp[(size_t)li2 << 7] = dtv;
    }
}

// ----------------------- selective scan, chunked ----------------------------
// Templated on direction K: gather index is affine in the unroll
// (mi = mib + i*STEP), so all loads/stores use immediate offsets.

template<int K>
__device__ __forceinline__ void scan1_body(int w, int lane,
                                           const float* __restrict__ A_logs)
{
    const int c = w & 7, dp = (w >> 3) & 63, b = w >> 11;
    const int d = dp * 2 + (lane >> 4);
    const int nn = lane & 15;
    const int kd = (K << 7) + d;
    const float A2 = -__expf(__ldg(&A_logs[(kd << 4) + nn])) * 1.442695041f;
    const float* dt_base = g_dtv + (((size_t)(b * 4 + K)) << 19) + d;
    const float* xd = g_xdbl + ((size_t)(b * 4 + K)) * 4096 * 36;
    const float* u_base = g_xins + (((size_t)(b * 128 + d)) << 12);
    constexpr int STEP = (K == 0) ? 1 : (K == 1) ? 64 : (K == 2) ? -1 : -64;

    float h = 0.f, P = 1.f;
    const int tend = (c + 1) << 9;
    for (int t0 = c << 9; t0 < tend; t0 += 8) {
        int mib;
        if (K == 0)      mib = t0;
        else if (K == 1) mib = ((t0 & 63) << 6) | (t0 >> 6);
        else if (K == 2) mib = 4095 - t0;
        else             mib = ((63 - (t0 & 63)) << 6) | (63 - (t0 >> 6));
        const float* dtp = dt_base + ((size_t)t0 << 7);
        const float* row = xd + (size_t)t0 * 36 + 4 + nn;
        const float* up  = u_base + mib;
        float dtv[8], Bv[8], uu[8];
#pragma unroll
        for (int i = 0; i < 8; i++) {
            dtv[i] = __ldg(dtp + (i << 7));
            Bv[i]  = __ldg(row + i * 36);
            uu[i]  = __ldg(up + i * STEP);
        }
#pragma unroll
        for (int i = 0; i < 8; i++) {
            float a = fexp2(dtv[i] * A2);
            h = fmaf(h, a, (dtv[i] * uu[i]) * Bv[i]);
            P *= a;
        }
    }
    g_hz[(w << 5) + lane] = h;
    g_P [(w << 5) + lane] = P;
}

__global__ __launch_bounds__(128)
void scan_p1(const float* __restrict__ A_logs)
{
    const int lane = threadIdx.x & 31;
    const int w = blockIdx.x * 4 + (threadIdx.x >> 5);
    const int k = (w >> 9) & 3;
    if (k == 0)      scan1_body<0>(w, lane, A_logs);
    else if (k == 1) scan1_body<1>(w, lane, A_logs);
    else if (k == 2) scan1_body<2>(w, lane, A_logs);
    else             scan1_body<3>(w, lane, A_logs);
}

template<int K>
__device__ __forceinline__ void scan2_body(int w, int lane,
                                           const float* __restrict__ A_logs,
                                           const float* __restrict__ Dsp)
{
    const int c = w & 7, dp = (w >> 3) & 63, b = w >> 11;
    const int d = dp * 2 + (lane >> 4);
    const int nn = lane & 15;
    const int kd = (K << 7) + d;
    const float A2 = -__expf(__ldg(&A_logs[(kd << 4) + nn])) * 1.442695041f;
    const float Dv = __ldg(&Dsp[kd]);
    const float* dt_base = g_dtv + (((size_t)(b * 4 + K)) << 19) + d;
    const float* xd = g_xdbl + ((size_t)(b * 4 + K)) * 4096 * 36;
    const float* u_base = g_xins + (((size_t)(b * 128 + d)) << 12);
    float* y_base = g_ydir + (size_t)K * YK + (((size_t)b) << 19) + d;
    constexpr int STEP = (K == 0) ? 1 : (K == 1) ? 64 : (K == 2) ? -1 : -64;

    float h = 0.f;
    for (int j = w - c; j < w; j++)
        h = fmaf(g_P[(j << 5) + lane], h, g_hz[(j << 5) + lane]);

    const int tend = (c + 1) << 9;
    for (int t0 = c << 9; t0 < tend; t0 += 8) {
        int mib;
        if (K == 0)      mib = t0;
        else if (K == 1) mib = ((t0 & 63) << 6) | (t0 >> 6);
        else if (K == 2) mib = 4095 - t0;
        else             mib = ((63 - (t0 & 63)) << 6) | (63 - (t0 >> 6));
        const float* dtp = dt_base + ((size_t)t0 << 7);
        const float* row = xd + (size_t)t0 * 36 + 4 + nn;
        const float* up  = u_base + mib;
        float* yp = y_base + ((size_t)mib << 7);
        float dtv[8], Bv[8], Cv[8], uu[8];
#pragma unroll
        for (int i = 0; i < 8; i++) {
            dtv[i] = __ldg(dtp + (i << 7));
            Bv[i]  = __ldg(row + i * 36);
            Cv[i]  = __ldg(row + i * 36 + 16);
            uu[i]  = __ldg(up + i * STEP);
        }
#pragma unroll
        for (int i = 0; i < 8; i++) {
            float a = fexp2(dtv[i] * A2);
            h = fmaf(h, a, (dtv[i] * uu[i]) * Bv[i]);
            float py = h * Cv[i];
            py += __shfl_xor_sync(0xffffffffu, py, 1);
            py += __shfl_xor_sync(0xffffffffu, py, 2);
            py += __shfl_xor_sync(0xffffffffu, py, 4);
            py += __shfl_xor_sync(0xffffffffu, py, 8);
            if (nn == 0) yp[i * STEP * 128] = fmaf(Dv, uu[i], py);
        }
    }
}

__global__ __launch_bounds__(128)
void scan_p2(const float* __restrict__ A_logs, const float* __restrict__ Dsp)
{
    const int lane = threadIdx.x & 31;
    const int w = blockIdx.x * 4 + (threadIdx.x >> 5);
    const int k = (w >> 9) & 3;
    if (k == 0)      scan2_body<0>(w, lane, A_logs, Dsp);
    else if (k == 1) scan2_body<1>(w, lane, A_logs, Dsp);
    else if (k == 2) scan2_body<2>(w, lane, A_logs, Dsp);
    else             scan2_body<3>(w, lane, A_logs, Dsp);
}

// - sum dirs, out-LN, *silu(z), out_proj, +skip*(t0+t1+cfb) -> res (NCHW) ----
__global__ __launch_bounds__(256)
void fuseout_k(const float* __restrict__ ong, const float* __restrict__ onb,
               const float* __restrict__ opw, const float* __restrict__ skipp,
               const float* __restrict__ cfb)
{
    __shared__ float s_opw[128 * 64];
    __shared__ float s_yn[8][132];
    const int t = threadIdx.x, wid = t >> 5, lane = t & 31;
    const float skip = __ldg(&skipp[0]);

    for (int idx = t; idx < 8192; idx += 256) {
        int c = idx >> 7, d = idx & 127;
        s_opw[(d << 6) + c] = opw[idx];
    }
    __syncthreads();

    const int d0 = lane << 2;
    const float4 gg = *(const float4*)(ong + d0);
    const float4 bb = *(const float4*)(onb + d0);
    const int c0 = lane, c1 = lane + 32;
    const float cb0 = __ldg(&cfb[c0]), cb1 = __ldg(&cfb[c1]);

    for (int i = 0; i < 4; i++) {
        int p = blockIdx.x * 32 + (wid << 2) + i;
        int b = p >> 12, l = p & 4095;
        size_t yo = (((size_t)p) << 7) + d0;
        float4 y  = *(const float4*)(g_ydir + yo);
        float4 y1 = *(const float4*)(g_ydir + (size_t)YK + yo);
        float4 y2 = *(const float4*)(g_ydir + 2 * (size_t)YK + yo);
        float4 y3 = *(const float4*)(g_ydir + 3 * (size_t)YK + yo);
        y.x += y1.x + y2.x + y3.x;  y.y += y1.y + y2.y + y3.y;
        y.z += y1.z + y2.z + y3.z;  y.w += y1.w + y2.w + y3.w;

        float s = y.x + y.y + y.z + y.w;
        float ss = y.x * y.x + y.y * y.y + y.z * y.z + y.w * y.w;
#pragma unroll
        for (int o = 16; o; o >>= 1) {
            s  += __shfl_xor_sync(0xffffffffu, s, o);
            ss += __shfl_xor_sync(0xffffffffu, ss, o);
        }
        float m = s * (1.f / 128.f);
        float rs = rsqrtf(ss * (1.f / 128.f) - m * m + EPSF);

        float4 zv = *(const float4*)(g_z + yo);
        float4 yn;
        yn.x = ((y.x - m) * rs * gg.x + bb.x) * zv.x;
        yn.y = ((y.y - m) * rs * gg.y + bb.y) * zv.y;
        yn.z = ((y.z - m) * rs * gg.z + bb.z) * zv.z;
        yn.w = ((y.w - m) * rs * gg.w + bb.w) * zv.w;
        __syncwarp();
        *(float4*)&s_yn[wid][d0] = yn;
        __syncwarp();

        float a0 = 0.f, a1 = 0.f;
#pragma unroll 8
        for (int d = 0; d < 128; d++) {
            float yv = s_yn[wid][d];
            a0 = fmaf(yv, s_opw[(d << 6) + c0], a0);
            a1 = fmaf(yv, s_opw[(d << 6) + c1], a1);
        }
        size_t o0 = (((size_t)(b * 64 + c0)) << 12) + l;
        size_t o1 = (((size_t)(b * 64 + c1)) << 12) + l;
        g_a[o0] = skip * (g_t0[o0] + g_t1[o0] + cb0) + a0;
        g_a[o1] = skip * (g_t0[o1] + g_t1[o1] + cb1) + a1;
    }
}

// ============================================================================
extern "C" void kernel_launch(void* const* d_in, const int* in_sizes, int n_in,
                              void* d_out, int out_size)
{
    const float* x       = (const float*)d_in[0];
    const float* conv1_w = (const float*)d_in[1];
    const float* conv1_b = (const float*)d_in[2];
    const float* conv2_w = (const float*)d_in[3];
    const float* conv2_b = (const float*)d_in[4];
    const float* cf_w    = (const float*)d_in[5];
    const float* cf_b    = (const float*)d_in[6];
    const float* ln_g    = (const float*)d_in[7];
    const float* ln_b    = (const float*)d_in[8];
    const float* in_proj = (const float*)d_in[9];
    const float* dw_w    = (const float*)d_in[10];
    const float* dw_b    = (const float*)d_in[11];
    const float* x_proj  = (const float*)d_in[12];
    const float* dt_w    = (const float*)d_in[13];
    const float* dt_b    = (const float*)d_in[14];
    const float* A_logs  = (const float*)d_in[15];
    const float* Ds      = (const float*)d_in[16];
    const float* on_g    = (const float*)d_in[17];
    const float* on_b    = (const float*)d_in[18];
    const float* op_w    = (const float*)d_in[19];
    const float* skip    = (const float*)d_in[20];
    const float* cb_w    = (const float*)d_in[21];
    const float* cb_b    = (const float*)d_in[22];
    float* out = (float*)d_out;

    float *ga, *gb, *t0, *t1, *t2, *t3;
    cudaGetSymbolAddress((void**)&ga, g_a);
    cudaGetSymbolAddress((void**)&gb, g_b);
    cudaGetSymbolAddress((void**)&t0, g_t0);
    cudaGetSymbolAddress((void**)&t1, g_t1);
    cudaGetSymbolAddress((void**)&t2, g_t2);
    cudaGetSymbolAddress((void**)&t3, g_t3);

    dim3 cgrid(16, 4, 16);
    conv3x3_k<<<cgrid, 128>>>(x, conv1_w, t0, t1);
    inorm2_k<<<256, 256>>>(t0, t1, conv1_b, nullptr, nullptr, nullptr, gb);
    conv3x3_k<<<cgrid, 128>>>(gb, conv2_w, t0, t1);
    combine_k<<<1024, 256>>>(ga, t0, t1, conv2_b);          // ga = mamba input
    conv3x3_k<<<cgrid, 128>>>(ga, cf_w, t0, t1);            // cf partials in t0,t1
    ln_inproj_k<<<256, 256>>>(in_proj, ln_g, ln_b, cf_b);
    dwconv_silu_k<<<8192, 256>>>(dw_w, dw_b);
    xdbl_k<<<dim3(128, 16), 256>>>(x_proj, dt_w, dt_b);
    scan_p1<<<NW / 4, 128>>>(A_logs);
    scan_p2<<<NW / 4, 128>>>(A_logs, Ds);
    fuseout_k<<<512, 256>>>(on_g, on_b, op_w, skip, cf_b);
    conv3x3_k<<<cgrid, 128>>>(ga, cb_w, t2, t3);
    inorm2_k<<<256, 256>>>(t2, t3, cb_b, t0, t1, cf_b, out);
}

// round 15
// speedup vs baseline: 1.3215x; 1.0853x over previous
#include <cuda_runtime.h>
#include <cstdint>
#include <cstddef>

#define BB 4
#define LL 4096
#define EPSF 1e-5f
#define YK (BB * LL * 128)
#define NW2 4096           // scan warps (b4 * k4 * dq32 * chunk8)

typedef unsigned long long ull;

__device__ __align__(256) float g_a   [BB * 64 * LL];
__device__ __align__(256) float g_b   [BB * 64 * LL];
__device__ __align__(256) float g_t0  [BB * 64 * LL];
__device__ __align__(256) float g_t1  [BB * 64 * LL];
__device__ __align__(256) float g_t2  [BB * 64 * LL];
__device__ __align__(256) float g_t3  [BB * 64 * LL];
__device__ __align__(256) float g_xin [BB * 128 * LL];
__device__ __align__(256) float g_xins[BB * 128 * LL];
__device__ __align__(256) float g_z   [BB * LL * 128];
__device__ __align__(256) float g_xdbl[BB * 4 * LL * 36];
__device__ __align__(256) float g_dtv [(size_t)BB * 4 * LL * 128];
__device__ __align__(256) float g_ydir[(size_t)4 * YK];
__device__ __align__(256) float g_P   [NW2 * 64];
__device__ __align__(256) float g_hz  [NW2 * 64];

// single-instruction exp2 on the MUFU pipe
__device__ __forceinline__ float fexp2(float x)
{
    float r;
    asm("ex2.approx.f32 %0, %1;" : "=f"(r) : "f"(x));
    return r;
}

// ---- packed f32x2 helpers (FFMA2/FMUL2 are PTX-only; ptxas won't auto-fuse)
__device__ __forceinline__ ull pk(float x, float y)
{
    ull r; asm("mov.b64 %0, {%1, %2};" : "=l"(r) : "f"(x), "f"(y)); return r;
}
__device__ __forceinline__ void upk(float& x, float& y, ull p)
{
    asm("mov.b64 {%0, %1}, %2;" : "=f"(x), "=f"(y) : "l"(p));
}
__device__ __forceinline__ ull mul2(ull a, ull b)
{
    ull r; asm("mul.rn.f32x2 %0, %1, %2;" : "=l"(r) : "l"(a), "l"(b)); return r;
}
__device__ __forceinline__ ull fma2(ull a, ull b, ull c)
{
    ull r; asm("fma.rn.f32x2 %0, %1, %2, %3;" : "=l"(r) : "l"(a), "l"(b), "l"(c));
    return r;
}

// ---------------- conv 3x3 SAME, 64->64, NCHW, cin-split partials -----------
// 128 threads, 2 vertical px x 8 out channels, register-prefetch pipeline.
__global__ __launch_bounds__(128)
void conv3x3_k(const float* __restrict__ in, const float* __restrict__ w,
               float* __restrict__ p0, float* __restrict__ p1)
{
    __shared__ float s_in[2592];
    __shared__ float s_w[576];
    const int tx = threadIdx.x & 15, ty = threadIdx.x >> 4, tid = threadIdx.x;
    const int txt = blockIdx.x & 3, tyt = blockIdx.x >> 2;
    const int b = blockIdx.y;
    const int cog = blockIdx.z & 7, half = blockIdx.z >> 3;
    float* outp = half ? p1 : p0;
    const int cib = half << 5;

    float acc0[8], acc1[8];
#pragma unroll
    for (int i = 0; i < 8; i++) { acc0[i] = 0.f; acc1[i] = 0.f; }

    float rin[21], rw[5];
    {
        const int ci0 = cib;
#pragma unroll
        for (int j = 0; j < 21; j++) {
            int idx = tid + (j << 7);
            float v = 0.f;
            if (j < 20 || idx < 2592) {
                int c2 = idx / 324, r = idx - c2 * 324;
                int iy = r / 18, ix = r - iy * 18;
                int gy = tyt * 16 + iy - 1, gx = txt * 16 + ix - 1;
                if ((unsigned)gy < 64u && (unsigned)gx < 64u)
                    v = in[(((size_t)(b * 64 + ci0 + c2)) << 12) + (gy << 6) + gx];
            }
            rin[j] = v;
        }
#pragma unroll
        for (int j = 0; j < 5; j++) {
            int idx = tid + (j << 7);
            if (j < 4 || idx < 576) {
                int co2 = idx / 72, r = idx - co2 * 72;
                int c2 = r / 9, tap = r - c2 * 9;
                rw[j] = w[(((cog * 8 + co2) * 64) + ci0 + c2) * 9 + tap];
            }
        }
    }

    for (int chunk = 0; chunk < 4; chunk++) {
        __syncthreads();
#pragma unroll
        for (int j = 0; j < 21; j++) {
            int idx = tid + (j << 7);
            if (j < 20 || idx < 2592) s_in[idx] = rin[j];
        }
#pragma unroll
        for (int j = 0; j < 5; j++) {
            int idx = tid + (j << 7);
            if (j < 4 || idx < 576) {
                int co2 = idx / 72, r = idx - co2 * 72;
                int c2 = r / 9, tap = r - c2 * 9;
                s_w[c2 * 72 + tap * 8 + co2] = rw[j];
            }
        }
        __syncthreads();

        if (chunk < 3) {
            const int ci0 = cib + (chunk + 1) * 8;
#pragma unroll
            for (int j = 0; j < 21; j++) {
                int idx = tid + (j << 7);
                float v = 0.f;
                if (j < 20 || idx < 2592) {
                    int c2 = idx / 324, r = idx - c2 * 324;
                    int iy = r / 18, ix = r - iy * 18;
                    int gy = tyt * 16 + iy - 1, gx = txt * 16 + ix - 1;
                    if ((unsigned)gy < 64u && (unsigned)gx < 64u)
                        v = in[(((size_t)(b * 64 + ci0 + c2)) << 12) + (gy << 6) + gx];
                }
                rin[j] = v;
            }
#pragma unroll
            for (int j = 0; j < 5; j++) {
                int idx = tid + (j << 7);
                if (j < 4 || idx < 576) {
                    int co2 = idx / 72, r = idx - co2 * 72;
                    int c2 = r / 9, tap = r - c2 * 9;
                    rw[j] = w[(((cog * 8 + co2) * 64) + ci0 + c2) * 9 + tap];
                }
            }
        }

#pragma unroll
        for (int c2 = 0; c2 < 8; c2++)
#pragma unroll
            for (int tap = 0; tap < 9; tap++) {
                const int dy = tap / 3, dx = tap - dy * 3;
                float iv0 = s_in[c2 * 324 + (2 * ty + dy) * 18 + tx + dx];
                float iv1 = s_in[c2 * 324 + (2 * ty + 1 + dy) * 18 + tx + dx];
                const float4* wp = (const float4*)&s_w[c2 * 72 + tap * 8];
                float4 w0 = wp[0], w1 = wp[1];
                acc0[0] = fmaf(iv0, w0.x, acc0[0]);  acc1[0] = fmaf(iv1, w0.x, acc1[0]);
                acc0[1] = fmaf(iv0, w0.y, acc0[1]);  acc1[1] = fmaf(iv1, w0.y, acc1[1]);
                acc0[2] = fmaf(iv0, w0.z, acc0[2]);  acc1[2] = fmaf(iv1, w0.z, acc1[2]);
                acc0[3] = fmaf(iv0, w0.w, acc0[3]);  acc1[3] = fmaf(iv1, w0.w, acc1[3]);
                acc0[4] = fmaf(iv0, w1.x, acc0[4]);  acc1[4] = fmaf(iv1, w1.x, acc1[4]);
                acc0[5] = fmaf(iv0, w1.y, acc0[5]);  acc1[5] = fmaf(iv1, w1.y, acc1[5]);
                acc0[6] = fmaf(iv0, w1.z, acc0[6]);  acc1[6] = fmaf(iv1, w1.z, acc1[6]);
                acc0[7] = fmaf(iv0, w1.w, acc0[7]);  acc1[7] = fmaf(iv1, w1.w, acc1[7]);
            }
    }
    const int y0 = tyt * 16 + 2 * ty, x = txt * 16 + tx;
#pragma unroll
    for (int c = 0; c < 8; c++) {
        int co = cog * 8 + c;
        size_t off0 = (((size_t)(b * 64 + co)) << 12) + (y0 << 6) + x;
        outp[off0] = acc0[c];
        outp[off0 + 64] = acc1[c];
    }
}

// -------- combine partials + bias --------------------------------------------
__global__ __launch_bounds__(256)
void combine_k(float* __restrict__ dst, const float* __restrict__ p0,
               const float* __restrict__ p1, const float* __restrict__ bias)
{
    int i = ((blockIdx.x << 8) + threadIdx.x) << 2;
    float bv = __ldg(&bias[(i >> 12) & 63]);
    float4 a = *(const float4*)(p0 + i);
    float4 b4 = *(const float4*)(p1 + i);
    float4 r;
    r.x = a.x + b4.x + bv;  r.y = a.y + b4.y + bv;
    r.z = a.z + b4.z + bv;  r.w = a.w + b4.w + bv;
    *(float4*)(dst + i) = r;
}

// --- combine partials + bias (+ optional add0+add1+addb) + inorm + lrelu ----
__global__ __launch_bounds__(256)
void inorm2_k(const float* __restrict__ p0, const float* __restrict__ p1,
              const float* __restrict__ bias,
              const float* __restrict__ add0, const float* __restrict__ add1,
              const float* __restrict__ addb, float* __restrict__ out)
{
    size_t base = ((size_t)blockIdx.x) << 12;
    const int ch = blockIdx.x & 63;
    const float bv = __ldg(&bias[ch]);
    const float av = add0 ? __ldg(&addb[ch]) : 0.f;
    int t = threadIdx.x;
    float v[16], s = 0.f, ss = 0.f;
#pragma unroll
    for (int i = 0; i < 16; i++) {
        size_t o = base + t + (i << 8);
        float xv = p0[o] + p1[o] + bv;
        if (add0) xv += add0[o] + add1[o] + av;
        v[i] = xv; s += xv; ss += xv * xv;
    }
#pragma unroll
    for (int o = 16; o; o >>= 1) {
        s  += __shfl_xor_sync(0xffffffffu, s, o);
        ss += __shfl_xor_sync(0xffffffffu, ss, o);
    }
    __shared__ float sa[8], sb[8];
    if ((t & 31) == 0) { sa[t >> 5] = s; sb[t >> 5] = ss; }
    __syncthreads();
    s = 0.f; ss = 0.f;
#pragma unroll
    for (int i = 0; i < 8; i++) { s += sa[i]; ss += sb[i]; }
    float m = s * (1.f / 4096.f);
    float rs = rsqrtf(ss * (1.f / 4096.f) - m * m + EPSF);
#pragma unroll
    for (int i = 0; i < 16; i++) {
        float xv = (v[i] - m) * rs;
        out[base + t + (i << 8)] = xv >= 0.f ? xv : 0.2f * xv;
    }
}

// - channel LN of x1(=t0+t1+cfb) + in_proj (256 outs); xin NCHW, silu(z) -----
__global__ __launch_bounds__(256)
void ln_inproj_k(const float* __restrict__ ipw,
                 const float* __restrict__ lng, const float* __restrict__ lnb,
                 const float* __restrict__ cfb)
{
    __shared__ float s_xn[64][68];
    const int t = threadIdx.x;
    float4 wr[16];
    const float4* wp = (const float4*)(ipw + t * 64);
#pragma unroll
    for (int i = 0; i < 16; i++) wr[i] = wp[i];

    const int wid = t >> 5, ln = t & 31;
    const float lg1 = __ldg(&lng[ln]),      lb1 = __ldg(&lnb[ln]);
    const float lg2 = __ldg(&lng[ln + 32]), lb2 = __ldg(&lnb[ln + 32]);
    const float cb1 = __ldg(&cfb[ln]),      cb2 = __ldg(&cfb[ln + 32]);

    for (int pl = wid; pl < 64; pl += 8) {
        int p = blockIdx.x * 64 + pl;
        int b = p >> 12, pp = p & 4095;
        size_t o1 = (((size_t)(b * 64 + ln)) << 12) + pp;
        size_t o2 = (((size_t)(b * 64 + ln + 32)) << 12) + pp;
        float v1 = g_t0[o1] + g_t1[o1] + cb1;
        float v2 = g_t0[o2] + g_t1[o2] + cb2;
        float s = v1 + v2, ss = v1 * v1 + v2 * v2;
#pragma unroll
        for (int o = 16; o; o >>= 1) {
            s  += __shfl_xor_sync(0xffffffffu, s, o);
            ss += __shfl_xor_sync(0xffffffffu, ss, o);
        }
        float m = s * (1.f / 64.f);
        float rs = rsqrtf(ss * (1.f / 64.f) - m * m + EPSF);
        s_xn[pl][ln]      = (v1 - m) * rs * lg1 + lb1;
        s_xn[pl][ln + 32] = (v2 - m) * rs * lg2 + lb2;
    }
    __syncthreads();

    for (int pl = 0; pl < 64; pl++) {
        const float4* xr = (const float4*)&s_xn[pl][0];
        float acc = 0.f;
#pragma unroll
        for (int i = 0; i < 16; i++) {
            float4 xv = xr[i];
            acc = fmaf(wr[i].x, xv.x, acc);
            acc = fmaf(wr[i].y, xv.y, acc);
            acc = fmaf(wr[i].z, xv.z, acc);
            acc = fmaf(wr[i].w, xv.w, acc);
        }
        int p = blockIdx.x * 64 + pl;
        int b = p >> 12, pp = p & 4095;
        if (t < 128) {
            g_xin[(((size_t)(b * 128 + t)) << 12) + pp] = acc;
        } else {
            float sg = 1.f / (1.f + __expf(-acc));
            g_z[(((size_t)p) << 7) + (t - 128)] = acc * sg;
        }
    }
}

// ------------------- depthwise conv 3x3 + silu ------------------------------
__global__ __launch_bounds__(256)
void dwconv_silu_k(const float* __restrict__ dww, const float* __restrict__ dwb)
{
    int idx = (blockIdx.x << 8) + threadIdx.x;
    int pp = idx & 4095;
    int d = (idx >> 12) & 127;
    int y = pp >> 6, x = pp & 63;
    const float* ip = g_xin + (((size_t)(idx >> 12)) << 12);
    float acc = __ldg(&dwb[d]);
#pragma unroll
    for (int dy = -1; dy <= 1; dy++)
#pragma unroll
        for (int dx = -1; dx <= 1; dx++) {
            int yy = y + dy, xx = x + dx;
            if ((unsigned)yy < 64u && (unsigned)xx < 64u)
                acc = fmaf(ip[(yy << 6) + xx],
                           __ldg(&dww[d * 9 + (dy + 1) * 3 + dx + 1]), acc);
        }
    float sg = 1.f / (1.f + __expf(-acc));
    g_xins[idx] = acc * sg;
}

// ----- x_proj (B/C to gmem) + dt_proj + softplus fused; gather fused --------
__global__ __launch_bounds__(256)
void xdbl_k(const float* __restrict__ xpw,
            const float* __restrict__ dtw, const float* __restrict__ dtb)
{
    __shared__ float s_u[128 * 32];
    __shared__ float s_w[128 * 36 + 16];
    __shared__ float s_dts[32][4];
    __shared__ float s_dtw[512];
    const int bk = blockIdx.y, b = bk >> 2, k = bk & 3;
    const int l0 = blockIdx.x * 32, t = threadIdx.x;

    for (int idx = t; idx < 36 * 128; idx += 256) {
        int c = idx >> 7, d = idx & 127;
        s_w[d * 36 + c] = xpw[((k * 36 + c) << 7) + d];
    }
    for (int idx = t; idx < 512; idx += 256)
        s_dtw[idx] = dtw[(k << 9) + idx];
    for (int idx = t; idx < 128 * 32; idx += 256) {
        int d = idx >> 5, li = idx & 31;
        int l = l0 + li;
        int ls = (k >= 2) ? (4095 - l) : l;
        int mi = (k & 1) ? (((ls & 63) << 6) | (ls >> 6)) : ls;
        s_u[(d << 5) + li] = g_xins[(((size_t)(b * 128 + d)) << 12) + mi];
    }
    __syncthreads();

    const int li = t & 31, cq = t >> 5;
    float a0 = 0.f, a1 = 0.f, a2 = 0.f, a3 = 0.f, a4 = 0.f;
#pragma unroll 4
    for (int d = 0; d < 128; d++) {
        float u = s_u[(d << 5) + li];
        const float* wrow = &s_w[d * 36 + cq];
        a0 = fmaf(u, wrow[0],  a0);
        a1 = fmaf(u, wrow[8],  a1);
        a2 = fmaf(u, wrow[16], a2);
        a3 = fmaf(u, wrow[24], a3);
        a4 = fmaf(u, wrow[32], a4);
    }
    size_t base = ((size_t)bk * 4096 + l0 + li) * 36 + cq;
    if (cq >= 4) g_xdbl[base] = a0;
    else         s_dts[li][cq] = a0;
    g_xdbl[base + 8]  = a1;
    g_xdbl[base + 16] = a2;
    g_xdbl[base + 24] = a3;
    if (cq < 4) g_xdbl[base + 32] = a4;
    __syncthreads();

    const int d = t & 127, lgrp = t >> 7;
    const float4 wv = *(const float4*)&s_dtw[d << 2];
    const float db = __ldg(&dtb[(k << 7) + d]);
    float* dtvp = g_dtv + (((size_t)bk * 4096 + l0) << 7) + d;
#pragma unroll
    for (int j = 0; j < 16; j++) {
        int li2 = lgrp * 16 + j;
        float4 q = *(const float4*)&s_dts[li2][0];
        float xv = fmaf(q.x, wv.x, fmaf(q.y, wv.y, fmaf(q.z, wv.z, q.w * wv.w))) + db;
        float dtv = fmaxf(xv, 0.f) + __logf(1.f + __expf(-fabsf(xv)));
        dtvp[(size_t)li2 << 7] = dtv;
    }
}

// ---------------- selective scan, chunked, f32x2-packed ---------------------
// Warp = 4 d-channels (d = dq*4 + g, g = lane>>3); lane owns states
// (2s, 2s+1), s = lane&7, packed as f32x2 (FFMA2/FMUL2).
// w = ((b*4+k)*32+dq)*8 + c ; 512 steps/chunk.

template<int K>
__device__ __forceinline__ void scan1_body(int w, int lane,
                                           const float* __restrict__ A_logs)
{
    const int c = w & 7, dq = (w >> 3) & 31, b = w >> 10;
    const int g = lane >> 3, s = lane & 7;
    const int d = dq * 4 + g;
    const int kd = (K << 7) + d;
    float2 al = *(const float2*)&A_logs[(kd << 4) + 2 * s];
    const float A2x = -__expf(al.x) * 1.442695041f;
    const float A2y = -__expf(al.y) * 1.442695041f;
    const float* dt_base = g_dtv + (((size_t)(b * 4 + K)) << 19) + d;
    const float* xd = g_xdbl + ((size_t)(b * 4 + K)) * 4096 * 36;
    const float* u_base = g_xins + (((size_t)(b * 128 + d)) << 12);
    constexpr int STEP = (K == 0) ? 1 : (K == 1) ? 64 : (K == 2) ? -1 : -64;

    ull h = pk(0.f, 0.f), P = pk(1.f, 1.f);
    const int tend = (c + 1) << 9;
    for (int t0 = c << 9; t0 < tend; t0 += 8) {
        int mib;
        if (K == 0)      mib = t0;
        else if (K == 1) mib = ((t0 & 63) << 6) | (t0 >> 6);
        else if (K == 2) mib = 4095 - t0;
        else             mib = ((63 - (t0 & 63)) << 6) | (63 - (t0 >> 6));
        const float* dtp = dt_base + ((size_t)t0 << 7);
        const float* row = xd + (size_t)t0 * 36 + 4 + 2 * s;
        const float* up  = u_base + mib;
        float dtv[8], uu[8]; ull Bv[8];
#pragma unroll
        for (int i = 0; i < 8; i++) {
            dtv[i] = __ldg(dtp + (i << 7));
            Bv[i]  = __ldg((const ull*)(row + i * 36));
            uu[i]  = __ldg(up + i * STEP);
        }
#pragma unroll
        for (int i = 0; i < 8; i++) {
            float ax = fexp2(dtv[i] * A2x);
            float ay = fexp2(dtv[i] * A2y);
            ull a = pk(ax, ay);
            float du = dtv[i] * uu[i];
            ull tt = mul2(pk(du, du), Bv[i]);
            h = fma2(h, a, tt);
            P = mul2(P, a);
        }
    }
    *(ull*)&g_hz[(w << 6) + (lane << 1)] = h;
    *(ull*)&g_P [(w << 6) + (lane << 1)] = P;
}

__global__ __launch_bounds__(128)
void scan_p1(const float* __restrict__ A_logs)
{
    const int lane = threadIdx.x & 31;
    const int w = blockIdx.x * 4 + (threadIdx.x >> 5);
    const int k = (w >> 8) & 3;
    if (k == 0)      scan1_body<0>(w, lane, A_logs);
    else if (k == 1) scan1_body<1>(w, lane, A_logs);
    else if (k == 2) scan1_body<2>(w, lane, A_logs);
    else             scan1_body<3>(w, lane, A_logs);
}

template<int K>
__device__ __forceinline__ void scan2_body(int w, int lane,
                                           const float* __restrict__ A_logs,
                                           const float* __restrict__ Dsp)
{
    const int c = w & 7, dq = (w >> 3) & 31, b = w >> 10;
    const int g = lane >> 3, s = lane & 7;
    const int d = dq * 4 + g;
    const int kd = (K << 7) + d;
    float2 al = *(const float2*)&A_logs[(kd << 4) + 2 * s];
    const float A2x = -__expf(al.x) * 1.442695041f;
    const float A2y = -__expf(al.y) * 1.442695041f;
    const float Dv = __ldg(&Dsp[kd]);
    const float* dt_base = g_dtv + (((size_t)(b * 4 + K)) << 19) + d;
    const float* xd = g_xdbl + ((size_t)(b * 4 + K)) * 4096 * 36;
    const float* u_base = g_xins + (((size_t)(b * 128 + d)) << 12);
    float* y_base = g_ydir + (size_t)K * YK + (((size_t)b) << 19) + d;
    constexpr int STEP = (K == 0) ? 1 : (K == 1) ? 64 : (K == 2) ? -1 : -64;

    ull h = pk(0.f, 0.f);
    for (int j = w - c; j < w; j++)
        h = fma2(*(const ull*)&g_P[(j << 6) + (lane << 1)], h,
                 *(const ull*)&g_hz[(j << 6) + (lane << 1)]);

    const int tend = (c + 1) << 9;
    for (int t0 = c << 9; t0 < tend; t0 += 8) {
        int mib;
        if (K == 0)      mib = t0;
        else if (K == 1) mib = ((t0 & 63) << 6) | (t0 >> 6);
        else if (K == 2) mib = 4095 - t0;
        else             mib = ((63 - (t0 & 63)) << 6) | (63 - (t0 >> 6));
        const float* dtp = dt_base + ((size_t)t0 << 7);
        const float* row = xd + (size_t)t0 * 36 + 4 + 2 * s;
        const float* up  = u_base + mib;
        float* yp = y_base + ((size_t)mib << 7);
        float dtv[8], uu[8]; ull Bv[8], Cv[8];
#pragma unroll
        for (int i = 0; i < 8; i++) {
            dtv[i] = __ldg(dtp + (i << 7));
            Bv[i]  = __ldg((const ull*)(row + i * 36));
            Cv[i]  = __ldg((const ull*)(row + i * 36 + 16));
            uu[i]  = __ldg(up + i * STEP);
        }
#pragma unroll
        for (int i = 0; i < 8; i++) {
            float ax = fexp2(dtv[i] * A2x);
            float ay = fexp2(dtv[i] * A2y);
            ull a = pk(ax, ay);
            float du = dtv[i] * uu[i];
            ull tt = mul2(pk(du, du), Bv[i]);
            h = fma2(h, a, tt);
            ull pyp = mul2(h, Cv[i]);
            float px, qy; upk(px, qy, pyp);
            float py = px + qy;
            py += __shfl_xor_sync(0xffffffffu, py, 1);
            py += __shfl_xor_sync(0xffffffffu, py, 2);
            py += __shfl_xor_sync(0xffffffffu, py, 4);
            if (s == 0) yp[i * STEP * 128] = fmaf(Dv, uu[i], py);
        }
    }
}

__global__ __launch_bounds__(128)
void scan_p2(const float* __restrict__ A_logs, const float* __restrict__ Dsp)
{
    const int lane = threadIdx.x & 31;
    const int w = blockIdx.x * 4 + (threadIdx.x >> 5);
    const int k = (w >> 8) & 3;
    if (k == 0)      scan2_body<0>(w, lane, A_logs, Dsp);
    else if (k == 1) scan2_body<1>(w, lane, A_logs, Dsp);
    else if (k == 2) scan2_body<2>(w, lane, A_logs, Dsp);
    else             scan2_body<3>(w, lane, A_logs, Dsp);
}

// - sum dirs, out-LN, *silu(z), out_proj, +skip*(t0+t1+cfb) -> res (NCHW) ----
__global__ __launch_bounds__(256)
void fuseout_k(const float* __restrict__ ong, const float* __restrict__ onb,
               const float* __restrict__ opw, const float* __restrict__ skipp,
               const float* __restrict__ cfb)
{
    __shared__ float s_opw[128 * 64];
    __shared__ float s_yn[8][132];
    const int t = threadIdx.x, wid = t >> 5, lane = t & 31;
    const float skip = __ldg(&skipp[0]);

    for (int idx = t; idx < 8192; idx += 256) {
        int c = idx >> 7, d = idx & 127;
        s_opw[(d << 6) + c] = opw[idx];
    }
    __syncthreads();

    const int d0 = lane << 2;
    const float4 gg = *(const float4*)(ong + d0);
    const float4 bb = *(const float4*)(onb + d0);
    const int c0 = lane, c1 = lane + 32;
    const float cb0 = __ldg(&cfb[c0]), cb1 = __ldg(&cfb[c1]);

    for (int i = 0; i < 4; i++) {
        int p = blockIdx.x * 32 + (wid << 2) + i;
        int b = p >> 12, l = p & 4095;
        size_t yo = (((size_t)p) << 7) + d0;
        float4 y  = *(const float4*)(g_ydir + yo);
        float4 y1 = *(const float4*)(g_ydir + (size_t)YK + yo);
        float4 y2 = *(const float4*)(g_ydir + 2 * (size_t)YK + yo);
        float4 y3 = *(const float4*)(g_ydir + 3 * (size_t)YK + yo);
        y.x += y1.x + y2.x + y3.x;  y.y += y1.y + y2.y + y3.y;
        y.z += y1.z + y2.z + y3.z;  y.w += y1.w + y2.w + y3.w;

        float s = y.x + y.y + y.z + y.w;
        float ss = y.x * y.x + y.y * y.y + y.z * y.z + y.w * y.w;
#pragma unroll
        for (int o = 16; o; o >>= 1) {
            s  += __shfl_xor_sync(0xffffffffu, s, o);
            ss += __shfl_xor_sync(0xffffffffu, ss, o);
        }
        float m = s * (1.f / 128.f);
        float rs = rsqrtf(ss * (1.f / 128.f) - m * m + EPSF);

        float4 zv = *(const float4*)(g_z + yo);
        float4 yn;
        yn.x = ((y.x - m) * rs * gg.x + bb.x) * zv.x;
        yn.y = ((y.y - m) * rs * gg.y + bb.y) * zv.y;
        yn.z = ((y.z - m) * rs * gg.z + bb.z) * zv.z;
        yn.w = ((y.w - m) * rs * gg.w + bb.w) * zv.w;
        __syncwarp();
        *(float4*)&s_yn[wid][d0] = yn;
        __syncwarp();

        float a0 = 0.f, a1 = 0.f;
#pragma unroll 8
        for (int d = 0; d < 128; d++) {
            float yv = s_yn[wid][d];
            a0 = fmaf(yv, s_opw[(d << 6) + c0], a0);
            a1 = fmaf(yv, s_opw[(d << 6) + c1], a1);
        }
        size_t o0 = (((size_t)(b * 64 + c0)) << 12) + l;
        size_t o1 = (((size_t)(b * 64 + c1)) << 12) + l;
        g_a[o0] = skip * (g_t0[o0] + g_t1[o0] + cb0) + a0;
        g_a[o1] = skip * (g_t0[o1] + g_t1[o1] + cb1) + a1;
    }
}

// ============================================================================
extern "C" void kernel_launch(void* const* d_in, const int* in_sizes, int n_in,
                              void* d_out, int out_size)
{
    const float* x       = (const float*)d_in[0];
    const float* conv1_w = (const float*)d_in[1];
    const float* conv1_b = (const float*)d_in[2];
    const float* conv2_w = (const float*)d_in[3];
    const float* conv2_b = (const float*)d_in[4];
    const float* cf_w    = (const float*)d_in[5];
    const float* cf_b    = (const float*)d_in[6];
    const float* ln_g    = (const float*)d_in[7];
    const float* ln_b    = (const float*)d_in[8];
    const float* in_proj = (const float*)d_in[9];
    const float* dw_w    = (const float*)d_in[10];
    const float* dw_b    = (const float*)d_in[11];
    const float* x_proj  = (const float*)d_in[12];
    const float* dt_w    = (const float*)d_in[13];
    const float* dt_b    = (const float*)d_in[14];
    const float* A_logs  = (const float*)d_in[15];
    const float* Ds      = (const float*)d_in[16];
    const float* on_g    = (const float*)d_in[17];
    const float* on_b    = (const float*)d_in[18];
    const float* op_w    = (const float*)d_in[19];
    const float* skip    = (const float*)d_in[20];
    const float* cb_w    = (const float*)d_in[21];
    const float* cb_b    = (const float*)d_in[22];
    float* out = (float*)d_out;

    float *ga, *gb, *t0, *t1, *t2, *t3;
    cudaGetSymbolAddress((void**)&ga, g_a);
    cudaGetSymbolAddress((void**)&gb, g_b);
    cudaGetSymbolAddress((void**)&t0, g_t0);
    cudaGetSymbolAddress((void**)&t1, g_t1);
    cudaGetSymbolAddress((void**)&t2, g_t2);
    cudaGetSymbolAddress((void**)&t3, g_t3);

    dim3 cgrid(16, 4, 16);
    conv3x3_k<<<cgrid, 128>>>(x, conv1_w, t0, t1);
    inorm2_k<<<256, 256>>>(t0, t1, conv1_b, nullptr, nullptr, nullptr, gb);
    conv3x3_k<<<cgrid, 128>>>(gb, conv2_w, t0, t1);
    combine_k<<<1024, 256>>>(ga, t0, t1, conv2_b);          // ga = mamba input
    conv3x3_k<<<cgrid, 128>>>(ga, cf_w, t0, t1);            // cf partials in t0,t1
    ln_inproj_k<<<256, 256>>>(in_proj, ln_g, ln_b, cf_b);
    dwconv_silu_k<<<8192, 256>>>(dw_w, dw_b);
    xdbl_k<<<dim3(128, 16), 256>>>(x_proj, dt_w, dt_b);
    scan_p1<<<NW2 / 4, 128>>>(A_logs);
    scan_p2<<<NW2 / 4, 128>>>(A_logs, Ds);
    fuseout_k<<<512, 256>>>(on_g, on_b, op_w, skip, cf_b);
    conv3x3_k<<<cgrid, 128>>>(ga, cb_w, t2, t3);
    inorm2_k<<<256, 256>>>(t2, t3, cb_b, t0, t1, cf_b, out);
}

// round 16
// speedup vs baseline: 1.3439x; 1.0170x over previous
#include <cuda_runtime.h>
#include <cstdint>
#include <cstddef>

#define BB 4
#define LL 4096
#define EPSF 1e-5f
#define YK (BB * LL * 128)
#define NW2 4096           // scan warps (b4 * k4 * dq32 * chunk8)

typedef unsigned long long ull;

__device__ __align__(256) float g_a   [BB * 64 * LL];
__device__ __align__(256) float g_b   [BB * 64 * LL];
__device__ __align__(256) float g_t0  [BB * 64 * LL];
__device__ __align__(256) float g_t1  [BB * 64 * LL];
__device__ __align__(256) float g_t2  [BB * 64 * LL];
__device__ __align__(256) float g_t3  [BB * 64 * LL];
__device__ __align__(256) float g_xin [BB * 128 * LL];
__device__ __align__(256) float g_xins[BB * 128 * LL];
__device__ __align__(256) float g_z   [BB * LL * 128];
__device__ __align__(256) float g_xdbl[BB * 4 * LL * 36];
__device__ __align__(256) float g_dtv [(size_t)BB * 4 * LL * 128];
__device__ __align__(256) float g_ydir[(size_t)4 * YK];
__device__ __align__(256) float g_P   [NW2 * 64];
__device__ __align__(256) float g_hz  [NW2 * 64];

// single-instruction exp2 on the MUFU pipe
__device__ __forceinline__ float fexp2(float x)
{
    float r;
    asm("ex2.approx.f32 %0, %1;" : "=f"(r) : "f"(x));
    return r;
}

// ---- packed f32x2 helpers (FFMA2/FMUL2 are PTX-only; ptxas won't auto-fuse)
__device__ __forceinline__ ull pk(float x, float y)
{
    ull r; asm("mov.b64 %0, {%1, %2};" : "=l"(r) : "f"(x), "f"(y)); return r;
}
__device__ __forceinline__ void upk(float& x, float& y, ull p)
{
    asm("mov.b64 {%0, %1}, %2;" : "=f"(x), "=f"(y) : "l"(p));
}
__device__ __forceinline__ ull mul2(ull a, ull b)
{
    ull r; asm("mul.rn.f32x2 %0, %1, %2;" : "=l"(r) : "l"(a), "l"(b)); return r;
}
__device__ __forceinline__ ull fma2(ull a, ull b, ull c)
{
    ull r; asm("fma.rn.f32x2 %0, %1, %2, %3;" : "=l"(r) : "l"(a), "l"(b), "l"(c));
    return r;
}

// ---------------- conv 3x3 SAME, 64->64, NCHW, cin-split partials -----------
// 128 threads, 2 vertical px x 8 out channels, register-prefetch pipeline.
// Inner loop packed f32x2: 8 FFMA2 replace 16 FFMA per (cin, tap, 2px).
__global__ __launch_bounds__(128)
void conv3x3_k(const float* __restrict__ in, const float* __restrict__ w,
               float* __restrict__ p0, float* __restrict__ p1)
{
    __shared__ float s_in[2592];
    __shared__ float s_w[576];
    const int tx = threadIdx.x & 15, ty = threadIdx.x >> 4, tid = threadIdx.x;
    const int txt = blockIdx.x & 3, tyt = blockIdx.x >> 2;
    const int b = blockIdx.y;
    const int cog = blockIdx.z & 7, half = blockIdx.z >> 3;
    float* outp = half ? p1 : p0;
    const int cib = half << 5;

    ull acc0[4], acc1[4];
    const ull z0 = pk(0.f, 0.f);
#pragma unroll
    for (int i = 0; i < 4; i++) { acc0[i] = z0; acc1[i] = z0; }

    float rin[21], rw[5];
    {
        const int ci0 = cib;
#pragma unroll
        for (int j = 0; j < 21; j++) {
            int idx = tid + (j << 7);
            float v = 0.f;
            if (j < 20 || idx < 2592) {
                int c2 = idx / 324, r = idx - c2 * 324;
                int iy = r / 18, ix = r - iy * 18;
                int gy = tyt * 16 + iy - 1, gx = txt * 16 + ix - 1;
                if ((unsigned)gy < 64u && (unsigned)gx < 64u)
                    v = in[(((size_t)(b * 64 + ci0 + c2)) << 12) + (gy << 6) + gx];
            }
            rin[j] = v;
        }
#pragma unroll
        for (int j = 0; j < 5; j++) {
            int idx = tid + (j << 7);
            if (j < 4 || idx < 576) {
                int co2 = idx / 72, r = idx - co2 * 72;
                int c2 = r / 9, tap = r - c2 * 9;
                rw[j] = w[(((cog * 8 + co2) * 64) + ci0 + c2) * 9 + tap];
            }
        }
    }

    for (int chunk = 0; chunk < 4; chunk++) {
        __syncthreads();
#pragma unroll
        for (int j = 0; j < 21; j++) {
            int idx = tid + (j << 7);
            if (j < 20 || idx < 2592) s_in[idx] = rin[j];
        }
#pragma unroll
        for (int j = 0; j < 5; j++) {
            int idx = tid + (j << 7);
            if (j < 4 || idx < 576) {
                int co2 = idx / 72, r = idx - co2 * 72;
                int c2 = r / 9, tap = r - c2 * 9;
                s_w[c2 * 72 + tap * 8 + co2] = rw[j];
            }
        }
        __syncthreads();

        if (chunk < 3) {
            const int ci0 = cib + (chunk + 1) * 8;
#pragma unroll
            for (int j = 0; j < 21; j++) {
                int idx = tid + (j << 7);
                float v = 0.f;
                if (j < 20 || idx < 2592) {
                    int c2 = idx / 324, r = idx - c2 * 324;
                    int iy = r / 18, ix = r - iy * 18;
                    int gy = tyt * 16 + iy - 1, gx = txt * 16 + ix - 1;
                    if ((unsigned)gy < 64u && (unsigned)gx < 64u)
                        v = in[(((size_t)(b * 64 + ci0 + c2)) << 12) + (gy << 6) + gx];
                }
                rin[j] = v;
            }
#pragma unroll
            for (int j = 0; j < 5; j++) {
                int idx = tid + (j << 7);
                if (j < 4 || idx < 576) {
                    int co2 = idx / 72, r = idx - co2 * 72;
                    int c2 = r / 9, tap = r - c2 * 9;
                    rw[j] = w[(((cog * 8 + co2) * 64) + ci0 + c2) * 9 + tap];
                }
            }
        }

#pragma unroll
        for (int c2 = 0; c2 < 8; c2++)
#pragma unroll
            for (int tap = 0; tap < 9; tap++) {
                const int dy = tap / 3, dx = tap - dy * 3;
                float iv0 = s_in[c2 * 324 + (2 * ty + dy) * 18 + tx + dx];
                float iv1 = s_in[c2 * 324 + (2 * ty + 1 + dy) * 18 + tx + dx];
                ull iv0p = pk(iv0, iv0), iv1p = pk(iv1, iv1);
                const ull* wp = (const ull*)&s_w[c2 * 72 + tap * 8];
                ull w0 = wp[0], w1 = wp[1], w2 = wp[2], w3 = wp[3];
                acc0[0] = fma2(iv0p, w0, acc0[0]);  acc1[0] = fma2(iv1p, w0, acc1[0]);
                acc0[1] = fma2(iv0p, w1, acc0[1]);  acc1[1] = fma2(iv1p, w1, acc1[1]);
                acc0[2] = fma2(iv0p, w2, acc0[2]);  acc1[2] = fma2(iv1p, w2, acc1[2]);
                acc0[3] = fma2(iv0p, w3, acc0[3]);  acc1[3] = fma2(iv1p, w3, acc1[3]);
            }
    }
    const int y0 = tyt * 16 + 2 * ty, x = txt * 16 + tx;
#pragma unroll
    for (int cp = 0; cp < 4; cp++) {
        float a0x, a0y, a1x, a1y;
        upk(a0x, a0y, acc0[cp]);
        upk(a1x, a1y, acc1[cp]);
        int co = cog * 8 + cp * 2;
        size_t offA = (((size_t)(b * 64 + co)) << 12) + (y0 << 6) + x;
        size_t offB = offA + (1 << 12);
        outp[offA] = a0x;       outp[offA + 64] = a1x;
        outp[offB] = a0y;       outp[offB + 64] = a1y;
    }
}

// -------- combine partials + bias --------------------------------------------
__global__ __launch_bounds__(256)
void combine_k(float* __restrict__ dst, const float* __restrict__ p0,
               const float* __restrict__ p1, const float* __restrict__ bias)
{
    int i = ((blockIdx.x << 8) + threadIdx.x) << 2;
    float bv = __ldg(&bias[(i >> 12) & 63]);
    float4 a = *(const float4*)(p0 + i);
    float4 b4 = *(const float4*)(p1 + i);
    float4 r;
    r.x = a.x + b4.x + bv;  r.y = a.y + b4.y + bv;
    r.z = a.z + b4.z + bv;  r.w = a.w + b4.w + bv;
    *(float4*)(dst + i) = r;
}

// --- combine partials + bias (+ optional add0+add1+addb) + inorm + lrelu ----
__global__ __launch_bounds__(256)
void inorm2_k(const float* __restrict__ p0, const float* __restrict__ p1,
              const float* __restrict__ bias,
              const float* __restrict__ add0, const float* __restrict__ add1,
              const float* __restrict__ addb, float* __restrict__ out)
{
    size_t base = ((size_t)blockIdx.x) << 12;
    const int ch = blockIdx.x & 63;
    const float bv = __ldg(&bias[ch]);
    const float av = add0 ? __ldg(&addb[ch]) : 0.f;
    int t = threadIdx.x;
    float v[16], s = 0.f, ss = 0.f;
#pragma unroll
    for (int i = 0; i < 16; i++) {
        size_t o = base + t + (i << 8);
        float xv = p0[o] + p1[o] + bv;
        if (add0) xv += add0[o] + add1[o] + av;
        v[i] = xv; s += xv; ss += xv * xv;
    }
#pragma unroll
    for (int o = 16; o; o >>= 1) {
        s  += __shfl_xor_sync(0xffffffffu, s, o);
        ss += __shfl_xor_sync(0xffffffffu, ss, o);
    }
    __shared__ float sa[8], sb[8];
    if ((t & 31) == 0) { sa[t >> 5] = s; sb[t >> 5] = ss; }
    __syncthreads();
    s = 0.f; ss = 0.f;
#pragma unroll
    for (int i = 0; i < 8; i++) { s += sa[i]; ss += sb[i]; }
    float m = s * (1.f / 4096.f);
    float rs = rsqrtf(ss * (1.f / 4096.f) - m * m + EPSF);
#pragma unroll
    for (int i = 0; i < 16; i++) {
        float xv = (v[i] - m) * rs;
        out[base + t + (i << 8)] = xv >= 0.f ? xv : 0.2f * xv;
    }
}

// - channel LN of x1(=t0+t1+cfb) + in_proj (256 outs); xin NCHW, silu(z) -----
__global__ __launch_bounds__(256)
void ln_inproj_k(const float* __restrict__ ipw,
                 const float* __restrict__ lng, const float* __restrict__ lnb,
                 const float* __restrict__ cfb)
{
    __shared__ float s_xn[64][68];
    const int t = threadIdx.x;
    float4 wr[16];
    const float4* wp = (const float4*)(ipw + t * 64);
#pragma unroll
    for (int i = 0; i < 16; i++) wr[i] = wp[i];

    const int wid = t >> 5, ln = t & 31;
    const float lg1 = __ldg(&lng[ln]),      lb1 = __ldg(&lnb[ln]);
    const float lg2 = __ldg(&lng[ln + 32]), lb2 = __ldg(&lnb[ln + 32]);
    const float cb1 = __ldg(&cfb[ln]),      cb2 = __ldg(&cfb[ln + 32]);

    for (int pl = wid; pl < 64; pl += 8) {
        int p = blockIdx.x * 64 + pl;
        int b = p >> 12, pp = p & 4095;
        size_t o1 = (((size_t)(b * 64 + ln)) << 12) + pp;
        size_t o2 = (((size_t)(b * 64 + ln + 32)) << 12) + pp;
        float v1 = g_t0[o1] + g_t1[o1] + cb1;
        float v2 = g_t0[o2] + g_t1[o2] + cb2;
        float s = v1 + v2, ss = v1 * v1 + v2 * v2;
#pragma unroll
        for (int o = 16; o; o >>= 1) {
            s  += __shfl_xor_sync(0xffffffffu, s, o);
            ss += __shfl_xor_sync(0xffffffffu, ss, o);
        }
        float m = s * (1.f / 64.f);
        float rs = rsqrtf(ss * (1.f / 64.f) - m * m + EPSF);
        s_xn[pl][ln]      = (v1 - m) * rs * lg1 + lb1;
        s_xn[pl][ln + 32] = (v2 - m) * rs * lg2 + lb2;
    }
    __syncthreads();

    for (int pl = 0; pl < 64; pl++) {
        const float4* xr = (const float4*)&s_xn[pl][0];
        float acc = 0.f;
#pragma unroll
        for (int i = 0; i < 16; i++) {
            float4 xv = xr[i];
            acc = fmaf(wr[i].x, xv.x, acc);
            acc = fmaf(wr[i].y, xv.y, acc);
            acc = fmaf(wr[i].z, xv.z, acc);
            acc = fmaf(wr[i].w, xv.w, acc);
        }
        int p = blockIdx.x * 64 + pl;
        int b = p >> 12, pp = p & 4095;
        if (t < 128) {
            g_xin[(((size_t)(b * 128 + t)) << 12) + pp] = acc;
        } else {
            float sg = 1.f / (1.f + __expf(-acc));
            g_z[(((size_t)p) << 7) + (t - 128)] = acc * sg;
        }
    }
}

// ------------------- depthwise conv 3x3 + silu ------------------------------
__global__ __launch_bounds__(256)
void dwconv_silu_k(const float* __restrict__ dww, const float* __restrict__ dwb)
{
    int idx = (blockIdx.x << 8) + threadIdx.x;
    int pp = idx & 4095;
    int d = (idx >> 12) & 127;
    int y = pp >> 6, x = pp & 63;
    const float* ip = g_xin + (((size_t)(idx >> 12)) << 12);
    float acc = __ldg(&dwb[d]);
#pragma unroll
    for (int dy = -1; dy <= 1; dy++)
#pragma unroll
        for (int dx = -1; dx <= 1; dx++) {
            int yy = y + dy, xx = x + dx;
            if ((unsigned)yy < 64u && (unsigned)xx < 64u)
                acc = fmaf(ip[(yy << 6) + xx],
                           __ldg(&dww[d * 9 + (dy + 1) * 3 + dx + 1]), acc);
        }
    float sg = 1.f / (1.f + __expf(-acc));
    g_xins[idx] = acc * sg;
}

// ----- x_proj (B/C to gmem) + dt_proj + softplus fused; gather fused --------
__global__ __launch_bounds__(256)
void xdbl_k(const float* __restrict__ xpw,
            const float* __restrict__ dtw, const float* __restrict__ dtb)
{
    __shared__ float s_u[128 * 32];
    __shared__ float s_w[128 * 36 + 16];
    __shared__ float s_dts[32][4];
    __shared__ float s_dtw[512];
    const int bk = blockIdx.y, b = bk >> 2, k = bk & 3;
    const int l0 = blockIdx.x * 32, t = threadIdx.x;

    for (int idx = t; idx < 36 * 128; idx += 256) {
        int c = idx >> 7, d = idx & 127;
        s_w[d * 36 + c] = xpw[((k * 36 + c) << 7) + d];
    }
    for (int idx = t; idx < 512; idx += 256)
        s_dtw[idx] = dtw[(k << 9) + idx];
    for (int idx = t; idx < 128 * 32; idx += 256) {
        int d = idx >> 5, li = idx & 31;
        int l = l0 + li;
        int ls = (k >= 2) ? (4095 - l) : l;
        int mi = (k & 1) ? (((ls & 63) << 6) | (ls >> 6)) : ls;
        s_u[(d << 5) + li] = g_xins[(((size_t)(b * 128 + d)) << 12) + mi];
    }
    __syncthreads();

    const int li = t & 31, cq = t >> 5;
    float a0 = 0.f, a1 = 0.f, a2 = 0.f, a3 = 0.f, a4 = 0.f;
#pragma unroll 4
    for (int d = 0; d < 128; d++) {
        float u = s_u[(d << 5) + li];
        const float* wrow = &s_w[d * 36 + cq];
        a0 = fmaf(u, wrow[0],  a0);
        a1 = fmaf(u, wrow[8],  a1);
        a2 = fmaf(u, wrow[16], a2);
        a3 = fmaf(u, wrow[24], a3);
        a4 = fmaf(u, wrow[32], a4);
    }
    size_t base = ((size_t)bk * 4096 + l0 + li) * 36 + cq;
    if (cq >= 4) g_xdbl[base] = a0;
    else         s_dts[li][cq] = a0;
    g_xdbl[base + 8]  = a1;
    g_xdbl[base + 16] = a2;
    g_xdbl[base + 24] = a3;
    if (cq < 4) g_xdbl[base + 32] = a4;
    __syncthreads();

    const int d = t & 127, lgrp = t >> 7;
    const float4 wv = *(const float4*)&s_dtw[d << 2];
    const float db = __ldg(&dtb[(k << 7) + d]);
    float* dtvp = g_dtv + (((size_t)bk * 4096 + l0) << 7) + d;
#pragma unroll
    for (int j = 0; j < 16; j++) {
        int li2 = lgrp * 16 + j;
        float4 q = *(const float4*)&s_dts[li2][0];
        float xv = fmaf(q.x, wv.x, fmaf(q.y, wv.y, fmaf(q.z, wv.z, q.w * wv.w))) + db;
        float dtv = fmaxf(xv, 0.f) + __logf(1.f + __expf(-fabsf(xv)));
        dtvp[(size_t)li2 << 7] = dtv;
    }
}

// ---------------- selective scan, chunked, f32x2-packed ---------------------
// Warp = 4 d-channels (d = dq*4 + g, g = lane>>3); lane owns states
// (2s, 2s+1), s = lane&7, packed as f32x2.

template<int K>
__device__ __forceinline__ void scan1_body(int w, int lane,
                                           const float* __restrict__ A_logs)
{
    const int c = w & 7, dq = (w >> 3) & 31, b = w >> 10;
    const int g = lane >> 3, s = lane & 7;
    const int d = dq * 4 + g;
    const int kd = (K << 7) + d;
    float2 al = *(const float2*)&A_logs[(kd << 4) + 2 * s];
    const float A2x = -__expf(al.x) * 1.442695041f;
    const float A2y = -__expf(al.y) * 1.442695041f;
    const float* dt_base = g_dtv + (((size_t)(b * 4 + K)) << 19) + d;
    const float* xd = g_xdbl + ((size_t)(b * 4 + K)) * 4096 * 36;
    const float* u_base = g_xins + (((size_t)(b * 128 + d)) << 12);
    constexpr int STEP = (K == 0) ? 1 : (K == 1) ? 64 : (K == 2) ? -1 : -64;

    ull h = pk(0.f, 0.f), P = pk(1.f, 1.f);
    const int tend = (c + 1) << 9;
    for (int t0 = c << 9; t0 < tend; t0 += 8) {
        int mib;
        if (K == 0)      mib = t0;
        else if (K == 1) mib = ((t0 & 63) << 6) | (t0 >> 6);
        else if (K == 2) mib = 4095 - t0;
        else             mib = ((63 - (t0 & 63)) << 6) | (63 - (t0 >> 6));
        const float* dtp = dt_base + ((size_t)t0 << 7);
        const float* row = xd + (size_t)t0 * 36 + 4 + 2 * s;
        const float* up  = u_base + mib;
        float dtv[8], uu[8]; ull Bv[8];
#pragma unroll
        for (int i = 0; i < 8; i++) {
            dtv[i] = __ldg(dtp + (i << 7));
            Bv[i]  = __ldg((const ull*)(row + i * 36));
            uu[i]  = __ldg(up + i * STEP);
        }
#pragma unroll
        for (int i = 0; i < 8; i++) {
            float ax = fexp2(dtv[i] * A2x);
            float ay = fexp2(dtv[i] * A2y);
            ull a = pk(ax, ay);
            float du = dtv[i] * uu[i];
            ull tt = mul2(pk(du, du), Bv[i]);
            h = fma2(h, a, tt);
            P = mul2(P, a);
        }
    }
    *(ull*)&g_hz[(w << 6) + (lane << 1)] = h;
    *(ull*)&g_P [(w << 6) + (lane << 1)] = P;
}

__global__ __launch_bounds__(128)
void scan_p1(const float* __restrict__ A_logs)
{
    const int lane = threadIdx.x & 31;
    const int w = blockIdx.x * 4 + (threadIdx.x >> 5);
    const int k = (w >> 8) & 3;
    if (k == 0)      scan1_body<0>(w, lane, A_logs);
    else if (k == 1) scan1_body<1>(w, lane, A_logs);
    else if (k == 2) scan1_body<2>(w, lane, A_logs);
    else             scan1_body<3>(w, lane, A_logs);
}

template<int K>
__device__ __forceinline__ void scan2_body(int w, int lane,
                                           const float* __restrict__ A_logs,
                                           const float* __restrict__ Dsp)
{
    const int c = w & 7, dq = (w >> 3) & 31, b = w >> 10;
    const int g = lane >> 3, s = lane & 7;
    const int d = dq * 4 + g;
    const int kd = (K << 7) + d;
    float2 al = *(const float2*)&A_logs[(kd << 4) + 2 * s];
    const float A2x = -__expf(al.x) * 1.442695041f;
    const float A2y = -__expf(al.y) * 1.442695041f;
    const float Dv = __ldg(&Dsp[kd]);
    const float* dt_base = g_dtv + (((size_t)(b * 4 + K)) << 19) + d;
    const float* xd = g_xdbl + ((size_t)(b * 4 + K)) * 4096 * 36;
    const float* u_base = g_xins + (((size_t)(b * 128 + d)) << 12);
    float* y_base = g_ydir + (size_t)K * YK + (((size_t)b) << 19) + d;
    constexpr int STEP = (K == 0) ? 1 : (K == 1) ? 64 : (K == 2) ? -1 : -64;

    ull h = pk(0.f, 0.f);
    for (int j = w - c; j < w; j++)
        h = fma2(*(const ull*)&g_P[(j << 6) + (lane << 1)], h,
                 *(const ull*)&g_hz[(j << 6) + (lane << 1)]);

    const int tend = (c + 1) << 9;
    for (int t0 = c << 9; t0 < tend; t0 += 8) {
        int mib;
        if (K == 0)      mib = t0;
        else if (K == 1) mib = ((t0 & 63) << 6) | (t0 >> 6);
        else if (K == 2) mib = 4095 - t0;
        else             mib = ((63 - (t0 & 63)) << 6) | (63 - (t0 >> 6));
        const float* dtp = dt_base + ((size_t)t0 << 7);
        const float* row = xd + (size_t)t0 * 36 + 4 + 2 * s;
        const float* up  = u_base + mib;
        float* yp = y_base + ((size_t)mib << 7);
        float dtv[8], uu[8]; ull Bv[8], Cv[8];
#pragma unroll
        for (int i = 0; i < 8; i++) {
            dtv[i] = __ldg(dtp + (i << 7));
            Bv[i]  = __ldg((const ull*)(row + i * 36));
            Cv[i]  = __ldg((const ull*)(row + i * 36 + 16));
            uu[i]  = __ldg(up + i * STEP);
        }
#pragma unroll
        for (int i = 0; i < 8; i++) {
            float ax = fexp2(dtv[i] * A2x);
            float ay = fexp2(dtv[i] * A2y);
            ull a = pk(ax, ay);
            float du = dtv[i] * uu[i];
            ull tt = mul2(pk(du, du), Bv[i]);
            h = fma2(h, a, tt);
            ull pyp = mul2(h, Cv[i]);
            float px, qy; upk(px, qy, pyp);
            float py = px + qy;
            py += __shfl_xor_sync(0xffffffffu, py, 1);
            py += __shfl_xor_sync(0xffffffffu, py, 2);
            py += __shfl_xor_sync(0xffffffffu, py, 4);
            if (s == 0) yp[i * STEP * 128] = fmaf(Dv, uu[i], py);
        }
    }
}

__global__ __launch_bounds__(128)
void scan_p2(const float* __restrict__ A_logs, const float* __restrict__ Dsp)
{
    const int lane = threadIdx.x & 31;
    const int w = blockIdx.x * 4 + (threadIdx.x >> 5);
    const int k = (w >> 8) & 3;
    if (k == 0)      scan2_body<0>(w, lane, A_logs, Dsp);
    else if (k == 1) scan2_body<1>(w, lane, A_logs, Dsp);
    else if (k == 2) scan2_body<2>(w, lane, A_logs, Dsp);
    else             scan2_body<3>(w, lane, A_logs, Dsp);
}

// - sum dirs, out-LN, *silu(z), out_proj, +skip*(t0+t1+cfb) -> res (NCHW) ----
__global__ __launch_bounds__(256)
void fuseout_k(const float* __restrict__ ong, const float* __restrict__ onb,
               const float* __restrict__ opw, const float* __restrict__ skipp,
               const float* __restrict__ cfb)
{
    __shared__ float s_opw[128 * 64];
    __shared__ float s_yn[8][132];
    const int t = threadIdx.x, wid = t >> 5, lane = t & 31;
    const float skip = __ldg(&skipp[0]);

    for (int idx = t; idx < 8192; idx += 256) {
        int c = idx >> 7, d = idx & 127;
        s_opw[(d << 6) + c] = opw[idx];
    }
    __syncthreads();

    const int d0 = lane << 2;
    const float4 gg = *(const float4*)(ong + d0);
    const float4 bb = *(const float4*)(onb + d0);
    const int c0 = lane, c1 = lane + 32;
    const float cb0 = __ldg(&cfb[c0]), cb1 = __ldg(&cfb[c1]);

    for (int i = 0; i < 4; i++) {
        int p = blockIdx.x * 32 + (wid << 2) + i;
        int b = p >> 12, l = p & 4095;
        size_t yo = (((size_t)p) << 7) + d0;
        float4 y  = *(const float4*)(g_ydir + yo);
        float4 y1 = *(const float4*)(g_ydir + (size_t)YK + yo);
        float4 y2 = *(const float4*)(g_ydir + 2 * (size_t)YK + yo);
        float4 y3 = *(const float4*)(g_ydir + 3 * (size_t)YK + yo);
        y.x += y1.x + y2.x + y3.x;  y.y += y1.y + y2.y + y3.y;
        y.z += y1.z + y2.z + y3.z;  y.w += y1.w + y2.w + y3.w;

        float s = y.x + y.y + y.z + y.w;
        float ss = y.x * y.x + y.y * y.y + y.z * y.z + y.w * y.w;
#pragma unroll
        for (int o = 16; o; o >>= 1) {
            s  += __shfl_xor_sync(0xffffffffu, s, o);
            ss += __shfl_xor_sync(0xffffffffu, ss, o);
        }
        float m = s * (1.f / 128.f);
        float rs = rsqrtf(ss * (1.f / 128.f) - m * m + EPSF);

        float4 zv = *(const float4*)(g_z + yo);
        float4 yn;
        yn.x = ((y.x - m) * rs * gg.x + bb.x) * zv.x;
        yn.y = ((y.y - m) * rs * gg.y + bb.y) * zv.y;
        yn.z = ((y.z - m) * rs * gg.z + bb.z) * zv.z;
        yn.w = ((y.w - m) * rs * gg.w + bb.w) * zv.w;
        __syncwarp();
        *(float4*)&s_yn[wid][d0] = yn;
        __syncwarp();

        float a0 = 0.f, a1 = 0.f;
#pragma unroll 8
        for (int d = 0; d < 128; d++) {
            float yv = s_yn[wid][d];
            a0 = fmaf(yv, s_opw[(d << 6) + c0], a0);
            a1 = fmaf(yv, s_opw[(d << 6) + c1], a1);
        }
        size_t o0 = (((size_t)(b * 64 + c0)) << 12) + l;
        size_t o1 = (((size_t)(b * 64 + c1)) << 12) + l;
        g_a[o0] = skip * (g_t0[o0] + g_t1[o0] + cb0) + a0;
        g_a[o1] = skip * (g_t0[o1] + g_t1[o1] + cb1) + a1;
    }
}

// ============================================================================
extern "C" void kernel_launch(void* const* d_in, const int* in_sizes, int n_in,
                              void* d_out, int out_size)
{
    const float* x       = (const float*)d_in[0];
    const float* conv1_w = (const float*)d_in[1];
    const float* conv1_b = (const float*)d_in[2];
    const float* conv2_w = (const float*)d_in[3];
    const float* conv2_b = (const float*)d_in[4];
    const float* cf_w    = (const float*)d_in[5];
    const float* cf_b    = (const float*)d_in[6];
    const float* ln_g    = (const float*)d_in[7];
    const float* ln_b    = (const float*)d_in[8];
    const float* in_proj = (const float*)d_in[9];
    const float* dw_w    = (const float*)d_in[10];
    const float* dw_b    = (const float*)d_in[11];
    const float* x_proj  = (const float*)d_in[12];
    const float* dt_w    = (const float*)d_in[13];
    const float* dt_b    = (const float*)d_in[14];
    const float* A_logs  = (const float*)d_in[15];
    const float* Ds      = (const float*)d_in[16];
    const float* on_g    = (const float*)d_in[17];
    const float* on_b    = (const float*)d_in[18];
    const float* op_w    = (const float*)d_in[19];
    const float* skip    = (const float*)d_in[20];
    const float* cb_w    = (const float*)d_in[21];
    const float* cb_b    = (const float*)d_in[22];
    float* out = (float*)d_out;

    float *ga, *gb, *t0, *t1, *t2, *t3;
    cudaGetSymbolAddress((void**)&ga, g_a);
    cudaGetSymbolAddress((void**)&gb, g_b);
    cudaGetSymbolAddress((void**)&t0, g_t0);
    cudaGetSymbolAddress((void**)&t1, g_t1);
    cudaGetSymbolAddress((void**)&t2, g_t2);
    cudaGetSymbolAddress((void**)&t3, g_t3);

    dim3 cgrid(16, 4, 16);
    conv3x3_k<<<cgrid, 128>>>(x, conv1_w, t0, t1);
    inorm2_k<<<256, 256>>>(t0, t1, conv1_b, nullptr, nullptr, nullptr, gb);
    conv3x3_k<<<cgrid, 128>>>(gb, conv2_w, t0, t1);
    combine_k<<<1024, 256>>>(ga, t0, t1, conv2_b);          // ga = mamba input
    conv3x3_k<<<cgrid, 128>>>(ga, cf_w, t0, t1);            // cf partials in t0,t1
    ln_inproj_k<<<256, 256>>>(in_proj, ln_g, ln_b, cf_b);
    dwconv_silu_k<<<8192, 256>>>(dw_w, dw_b);
    xdbl_k<<<dim3(128, 16), 256>>>(x_proj, dt_w, dt_b);
    scan_p1<<<NW2 / 4, 128>>>(A_logs);
    scan_p2<<<NW2 / 4, 128>>>(A_logs, Ds);
    fuseout_k<<<512, 256>>>(on_g, on_b, op_w, skip, cf_b);
    conv3x3_k<<<cgrid, 128>>>(ga, cb_w, t2, t3);
    inorm2_k<<<256, 256>>>(t2, t3, cb_b, t0, t1, cf_b, out);
}